// round 6
// baseline (speedup 1.0000x reference)
#include <cuda_runtime.h>
#include <math.h>

#define B_ 8
#define C_ 64
#define H_ 256
#define W_ 512
#define KF 64            // modified W-frequency bins
#define NROW (B_*C_*H_)  // 131072 GEMM rows

typedef unsigned long long ull;

__device__ __forceinline__ ull pk2(float lo, float hi) {
    ull r; asm("mov.b64 %0, {%1, %2};" : "=l"(r) : "f"(lo), "f"(hi)); return r;
}
__device__ __forceinline__ void upk2(ull v, float& lo, float& hi) {
    asm("mov.b64 {%0, %1}, %2;" : "=f"(lo), "=f"(hi) : "l"(v));
}
#define FMA2(d, a, b) asm("fma.rn.f32x2 %0, %1, %2, %0;" : "+l"(d) : "l"(a), "l"(b))

// ---------------- static device scratch (allocation-free rule) ----------------
__device__ __align__(16) float  d_TF[W_ * 2 * KF];              // fwd twiddles [w][2k]
__device__ __align__(16) float  d_TI[2 * KF * W_];              // inv twiddles [2k][w]
__device__ __align__(16) float2 d_E[W_];                        // e^{2*pi*i*t/512}
__device__ __align__(16) float  d_xp[(size_t)NROW * KF];        // pooled x (b,c,h,j)
__device__ __align__(16) float2 d_G[B_ * H_ * KF];              // filt-1 (b,m,k)
__device__ __align__(16) float2 d_ker[B_ * KF * H_];            // circulant kernel (b,k,d)
__device__ __align__(16) float  d_U[(size_t)NROW * 2 * KF];     // fwd spectrum (b,c,h,k{r,i})
__device__ __align__(16) float2 d_U2[(size_t)B_ * KF * C_ * H_];// (b,k,c,h)
__device__ __align__(16) float2 d_V2[(size_t)B_ * KF * C_ * H_];// (b,k,c,n)
__device__ __align__(16) float  d_V[(size_t)NROW * 2 * KF];     // (b,c,n,k{r,i})

// ---------------- twiddle tables (double-precision generation) ----------------
__global__ void k_tables() {
    int t = blockIdx.x * 256 + threadIdx.x;     // 65536 threads
    if (t < 512) {
        double s, c; sincospi((double)t / 256.0, &s, &c);
        d_E[t] = make_float2((float)c, (float)s);
    }
    {   // TF[w][kk]: kk=2k -> cos(2pi wk/512), kk=2k+1 -> -sin
        int w = t >> 7, kk = t & 127, k = kk >> 1;
        int m = (w * k) & 511;
        double s, c; sincospi((double)m / 256.0, &s, &c);
        d_TF[t] = (kk & 1) ? (float)(-s) : (float)c;
    }
    {   // TI[kk][w]: kk=2k -> ck*cos, kk=2k+1 -> -ck*sin  (c0=1, ck=2)
        int kk = t >> 9, w = t & 511, k = kk >> 1;
        int m = (w * k) & 511;
        double s, c; sincospi((double)m / 256.0, &s, &c);
        float ck = (k == 0) ? 1.f : 2.f;
        d_TI[t] = (kk & 1) ? (float)(-ck * s) : (float)(ck * c);
    }
}

// ---------------- pooling: xp[b,c,h,j] = mean_{u<8} x[..., 8j+u] ----------------
__global__ void k_pool(const float* __restrict__ x) {
    int id = blockIdx.x * 256 + threadIdx.x;    // NROW*64 exactly
    int j = id & 63;
    size_t row = (size_t)(id >> 6);
    const float* p = x + row * W_ + j * 8;
    float4 a = *(const float4*)p, b = *(const float4*)(p + 4);
    d_xp[id] = (a.x + a.y + a.z + a.w + b.x + b.y + b.z + b.w) * 0.125f;
}

// ---------------- FFMA2 GEMM: C[128x128 tile] = scale*A*B (+X) ----------------
// block 256 threads, thread tile 8 rows x 8 cols (cols paired for f32x2)
template<bool ADDX>
__global__ void __launch_bounds__(256) k_gemm(
    const float* __restrict__ A, int lda,
    const float* __restrict__ Bm, int ldb,
    float* __restrict__ C, int ldc,
    const float* __restrict__ X, int K, float scale)
{
    __shared__ float As[32][132];   // [k][row], 16B-aligned rows
    __shared__ float Bs[32][128];   // [k][col]
    const int tid = threadIdx.x;
    const int tx = tid & 15;        // col group: cols tx*8 .. tx*8+7
    const int ty = tid >> 4;        // row group: rows ty*8 .. ty*8+7
    const long row0 = (long)blockIdx.x * 128;
    const int col0 = blockIdx.y * 128;

    ull acc[8][4];
#pragma unroll
    for (int u = 0; u < 8; u++)
#pragma unroll
        for (int v = 0; v < 4; v++) acc[u][v] = 0ull;

    for (int kc = 0; kc < K; kc += 32) {
        __syncthreads();
        // A tile 128 rows x 32 k, transposed into As[k][row]
#pragma unroll
        for (int i = 0; i < 4; i++) {
            int f = tid + i * 256;          // 1024 float4
            int r = f >> 3, q = f & 7;
            float4 v = *(const float4*)(A + (row0 + r) * lda + kc + q * 4);
            As[q * 4 + 0][r] = v.x; As[q * 4 + 1][r] = v.y;
            As[q * 4 + 2][r] = v.z; As[q * 4 + 3][r] = v.w;
        }
        // B tile 32 x 128
#pragma unroll
        for (int i = 0; i < 4; i++) {
            int f = tid + i * 256;
            int kk = f >> 5, q = f & 31;
            *(float4*)&Bs[kk][q * 4] =
                *(const float4*)(Bm + (long)(kc + kk) * ldb + col0 + q * 4);
        }
        __syncthreads();
#pragma unroll
        for (int kk = 0; kk < 32; kk++) {
            float4 a0 = *(const float4*)&As[kk][ty * 8];
            float4 a1 = *(const float4*)&As[kk][ty * 8 + 4];
            ull aa[8];
            aa[0] = pk2(a0.x, a0.x); aa[1] = pk2(a0.y, a0.y);
            aa[2] = pk2(a0.z, a0.z); aa[3] = pk2(a0.w, a0.w);
            aa[4] = pk2(a1.x, a1.x); aa[5] = pk2(a1.y, a1.y);
            aa[6] = pk2(a1.z, a1.z); aa[7] = pk2(a1.w, a1.w);
            ulonglong2 b0 = *(const ulonglong2*)&Bs[kk][tx * 8];
            ulonglong2 b1 = *(const ulonglong2*)&Bs[kk][tx * 8 + 4];
            ull bb[4] = { b0.x, b0.y, b1.x, b1.y };
#pragma unroll
            for (int u = 0; u < 8; u++)
#pragma unroll
                for (int v = 0; v < 4; v++)
                    FMA2(acc[u][v], aa[u], bb[v]);
        }
    }
#pragma unroll
    for (int u = 0; u < 8; u++) {
        long idx = (row0 + ty * 8 + u) * ldc + col0 + tx * 8;
        float o[8];
#pragma unroll
        for (int v = 0; v < 4; v++) upk2(acc[u][v], o[2 * v], o[2 * v + 1]);
        float4 r0, r1;
        if (ADDX) {
            float4 x0 = *(const float4*)(X + idx);
            float4 x1 = *(const float4*)(X + idx + 4);
            r0 = make_float4(fmaf(o[0], scale, x0.x), fmaf(o[1], scale, x0.y),
                             fmaf(o[2], scale, x0.z), fmaf(o[3], scale, x0.w));
            r1 = make_float4(fmaf(o[4], scale, x1.x), fmaf(o[5], scale, x1.y),
                             fmaf(o[6], scale, x1.z), fmaf(o[7], scale, x1.w));
        } else {
            r0 = make_float4(o[0] * scale, o[1] * scale, o[2] * scale, o[3] * scale);
            r1 = make_float4(o[4] * scale, o[5] * scale, o[6] * scale, o[7] * scale);
        }
        *(float4*)(C + idx) = r0;
        *(float4*)(C + idx + 4) = r1;
    }
}

// ---------------- filter: params GEMV + nonlinearities -> G = filt-1 ----------------
__global__ void __launch_bounds__(256) k_filter(
    const float* __restrict__ w, const float* __restrict__ bias,
    const float* __restrict__ dt)
{
    __shared__ float ws[4096];
    __shared__ float bs[64];
    int tid = threadIdx.x;
#pragma unroll
    for (int i = tid; i < 4096; i += 256) ws[i] = w[i];
    if (tid < 64) bs[tid] = bias[tid];
    __syncthreads();

    int id = blockIdx.x * 256 + tid;            // B*H*64 = 131072
    int j = id & 63, h = (id >> 6) & 255, bb = id >> 14;
    float xv[64];
#pragma unroll
    for (int c = 0; c < 64; c++)
        xv[c] = d_xp[(((size_t)(bb * 64 + c)) * 256 + h) * 64 + j];
    float dtb = dt[bb];
    float fr = 0.f, fi = 0.f;
    for (int r = 0; r < 32; r++) {
        float p1 = bs[r], p2 = bs[32 + r];
#pragma unroll
        for (int c = 0; c < 64; c++) {
            p1 = fmaf(ws[r * 64 + c], xv[c], p1);
            p2 = fmaf(ws[(32 + r) * 64 + c], xv[c], p2);
        }
        float nu  = log1pf(expf(p1));
        float th  = tanhf(p2) * 3.14159265358979323846f;
        float dec = expf(-nu * dtb);
        float s, co; sincosf(th * dtb, &s, &co);
        fr = fmaf(dec, co, fr);
        fi = fmaf(dec, s, fi);
    }
    d_G[id] = make_float2(fr - 1.f, fi);
}

// ---------------- circulant kernel: ker[b,k,d] = (1/256) sum_m G[b,m,k] e^{+2pi i dm/256} ----
__global__ void k_kern() {
    __shared__ float2 Gs[256];
    __shared__ float2 Es[256];
    int bk = blockIdx.x;                        // b*64+k
    int b = bk >> 6, k = bk & 63;
    int d = threadIdx.x;
    Gs[d] = d_G[((size_t)b * 256 + d) * 64 + k];
    Es[d] = d_E[2 * d];                         // e^{2pi i d/256}
    __syncthreads();
    float ar = 0.f, ai = 0.f;
    for (int m = 0; m < 256; m++) {
        int t = (d * m) & 255;
        float2 e = Es[t]; float2 g = Gs[m];
        ar += g.x * e.x - g.y * e.y;
        ai += g.x * e.y + g.y * e.x;
    }
    d_ker[(size_t)bk * 256 + d] = make_float2(ar * (1.f / 256.f), ai * (1.f / 256.f));
}

// ---------------- batched complex transpose: in (b,R,C) -> out (b,C,R) ----------------
__global__ void k_transpose(const float2* __restrict__ in, float2* __restrict__ out,
                            int R, int C)
{
    __shared__ float2 t[32][33];
    int c0 = blockIdx.x * 32, r0 = blockIdx.y * 32;
    int x = threadIdx.x, y = threadIdx.y;       // (32,8)
    size_t base = (size_t)blockIdx.z * R * C;
#pragma unroll
    for (int i = 0; i < 32; i += 8)
        t[y + i][x] = in[base + (size_t)(r0 + y + i) * C + c0 + x];
    __syncthreads();
#pragma unroll
    for (int i = 0; i < 32; i += 8)
        out[base + (size_t)(c0 + y + i) * R + r0 + x] = t[x][y + i];
}

// ---------------- H circulant conv (FFMA2): V2[b,k,c,n] = sum_h ker[b,k,(n-h)&255]*U2[b,k,c,h]
__global__ void __launch_bounds__(256) k_circ() {
    __shared__ ull kca[512];        // (kx, kx)
    __shared__ ull kcb[512];        // (-ky, ky)
    __shared__ ull Us[8][256];      // (ux, uy)
    __shared__ ull Uw[8][256];      // (uy, ux)
    int bk = blockIdx.x;            // 512 blocks
    int tid = threadIdx.x;
    const float2* kb = d_ker + (size_t)bk * 256;
#pragma unroll
    for (int i = 0; i < 2; i++) {
        int t = tid + i * 256;
        float2 kv = kb[t & 255];
        kca[t] = pk2(kv.x, kv.x);
        kcb[t] = pk2(-kv.y, kv.y);
    }
    const float2* Ub = d_U2 + (size_t)bk * (C_ * H_);
    float2*       Vb = d_V2 + (size_t)bk * (C_ * H_);
    const int n = tid;
    for (int cc = 0; cc < 64; cc += 8) {
        __syncthreads();
#pragma unroll
        for (int i = 0; i < 8; i++) {
            int f = tid + i * 256;
            int c = f >> 8, h = f & 255;
            float2 u = Ub[(cc + c) * 256 + h];
            Us[c][h] = pk2(u.x, u.y);
            Uw[c][h] = pk2(u.y, u.x);
        }
        __syncthreads();
        ull acc[8];
#pragma unroll
        for (int c = 0; c < 8; c++) acc[c] = 0ull;
#pragma unroll 4
        for (int h = 0; h < 256; h++) {
            ull ka = kca[n - h + 256];
            ull kb2 = kcb[n - h + 256];
#pragma unroll
            for (int c = 0; c < 8; c++) {
                FMA2(acc[c], ka, Us[c][h]);
                FMA2(acc[c], kb2, Uw[c][h]);
            }
        }
#pragma unroll
        for (int c = 0; c < 8; c++) {
            float ar, ai; upk2(acc[c], ar, ai);
            Vb[(cc + c) * 256 + n] = make_float2(ar, ai);
        }
    }
}

// ---------------- launch ----------------
extern "C" void kernel_launch(void* const* d_in, const int* in_sizes, int n_in,
                              void* d_out, int out_size) {
    const float* x    = (const float*)d_in[0];
    const float* dt   = (const float*)d_in[1];
    const float* w    = (const float*)d_in[2];
    const float* bias = (const float*)d_in[3];
    float* out = (float*)d_out;

    void *pTF, *pTI, *pU, *pU2, *pV2, *pV;
    cudaGetSymbolAddress(&pTF, d_TF);
    cudaGetSymbolAddress(&pTI, d_TI);
    cudaGetSymbolAddress(&pU,  d_U);
    cudaGetSymbolAddress(&pU2, d_U2);
    cudaGetSymbolAddress(&pV2, d_V2);
    cudaGetSymbolAddress(&pV,  d_V);

    k_tables<<<256, 256>>>();
    k_pool<<<NROW * 64 / 256, 256>>>(x);
    // K1: U = x * TF   (131072 x 512) * (512 x 128)
    k_gemm<false><<<dim3(NROW / 128, 1), 256>>>(
        x, W_, (const float*)pTF, 128, (float*)pU, 128, nullptr, W_, 1.f);
    k_filter<<<B_ * H_ * KF / 256, 256>>>(w, bias, dt);
    k_kern<<<B_ * KF, 256>>>();
    // T1: (b, c*h=16384, k=64) -> (b, k, c*h)
    k_transpose<<<dim3(2, 512, B_), dim3(32, 8)>>>(
        (const float2*)pU, (float2*)pU2, 16384, 64);
    k_circ<<<B_ * KF, 256>>>();
    // T2: (b, k=64, c*n=16384) -> (b, c*n, k)
    k_transpose<<<dim3(512, 2, B_), dim3(32, 8)>>>(
        (const float2*)pV2, (float2*)pV, 64, 16384);
    // K5: out = x + (1/512) * V * TI   (131072 x 128) * (128 x 512)
    k_gemm<true><<<dim3(NROW / 128, 4), 256>>>(
        (const float*)pV, 128, (const float*)pTI, W_, out, W_, x, 128, 1.f / 512.f);
}

// round 7
// speedup vs baseline: 1.4959x; 1.4959x over previous
#include <cuda_runtime.h>
#include <math.h>

#define B_ 8
#define C_ 64
#define H_ 256
#define W_ 512
#define KF 64            // modified W-frequency bins
#define NROW (B_*C_*H_)  // 131072 GEMM rows

// ---------------- static device scratch (allocation-free rule) ----------------
__device__ __align__(16) float  d_TF[W_ * 2 * KF];              // fwd twiddles [w][2k]
__device__ __align__(16) float  d_TI[2 * KF * W_];              // inv twiddles [2k][w]
__device__ __align__(16) float2 d_E[W_];                        // e^{+2*pi*i*t/512}
__device__ __align__(16) float  d_xp[(size_t)NROW * KF];        // pooled x (b,c,h,j)
__device__ __align__(16) float2 d_G[B_ * H_ * KF];              // (filt-1)/256  (b,m,k)
__device__ __align__(16) float  d_U[(size_t)NROW * 2 * KF];     // fwd spectrum (b,c,h,k{r,i})
__device__ __align__(16) float  d_V[(size_t)NROW * 2 * KF];     // filtered (b,c,n,k{r,i})

__device__ __forceinline__ float2 cadd(float2 a, float2 b){ return make_float2(a.x+b.x, a.y+b.y); }
__device__ __forceinline__ float2 csub(float2 a, float2 b){ return make_float2(a.x-b.x, a.y-b.y); }
__device__ __forceinline__ float2 cmul(float2 a, float2 b){
    return make_float2(fmaf(a.x,b.x,-a.y*b.y), fmaf(a.x,b.y,a.y*b.x));
}

// ---------------- in-register FFT16 (natural order in/out), INV=0 fwd, 1 inv ----
template<int INV>
__device__ __forceinline__ void fft16(float2* v) {
    const float C1 = 0.9238795325112867f, S1 = 0.3826834323650898f;
    const float C2 = 0.7071067811865476f;
    const float sg = INV ? 1.f : -1.f;
    const float2 w1 = make_float2( C1, sg*S1);
    const float2 w2 = make_float2( C2, sg*C2);
    const float2 w3 = make_float2( S1, sg*C1);
    const float2 w4 = make_float2(0.f, sg);
    const float2 w6 = make_float2(-C2, sg*C2);
    const float2 w9 = make_float2(-C1, -sg*S1);
    float2 A[16];
#pragma unroll
    for (int n0 = 0; n0 < 4; n0++) {
        float2 a=v[n0], b=v[n0+4], c=v[n0+8], d=v[n0+12];
        float2 t0=cadd(a,c), t1=csub(a,c), t2=cadd(b,d), t3=csub(b,d);
        float2 jt3 = INV ? make_float2(-t3.y, t3.x) : make_float2(t3.y, -t3.x);
        A[n0*4+0]=cadd(t0,t2); A[n0*4+1]=cadd(t1,jt3);
        A[n0*4+2]=csub(t0,t2); A[n0*4+3]=csub(t1,jt3);
    }
    A[5]=cmul(A[5],w1);  A[6]=cmul(A[6],w2);  A[7]=cmul(A[7],w3);
    A[9]=cmul(A[9],w2);  A[10]=cmul(A[10],w4); A[11]=cmul(A[11],w6);
    A[13]=cmul(A[13],w3); A[14]=cmul(A[14],w6); A[15]=cmul(A[15],w9);
#pragma unroll
    for (int k1 = 0; k1 < 4; k1++) {
        float2 a=A[k1], b=A[4+k1], c=A[8+k1], d=A[12+k1];
        float2 t0=cadd(a,c), t1=csub(a,c), t2=cadd(b,d), t3=csub(b,d);
        float2 jt3 = INV ? make_float2(-t3.y, t3.x) : make_float2(t3.y, -t3.x);
        v[k1+0]=cadd(t0,t2); v[k1+4]=cadd(t1,jt3);
        v[k1+8]=csub(t0,t2); v[k1+12]=csub(t1,jt3);
    }
}

// ---------------- twiddle tables (double-precision generation) ----------------
__global__ void k_tables() {
    int t = blockIdx.x * 256 + threadIdx.x;     // 65536 threads
    if (t < 512) {
        double s, c; sincospi((double)t / 256.0, &s, &c);
        d_E[t] = make_float2((float)c, (float)s);
    }
    {   // TF[w][kk]: kk=2k -> cos(2pi wk/512), kk=2k+1 -> -sin
        int w = t >> 7, kk = t & 127, k = kk >> 1;
        int m = (w * k) & 511;
        double s, c; sincospi((double)m / 256.0, &s, &c);
        d_TF[t] = (kk & 1) ? (float)(-s) : (float)c;
    }
    {   // TI[kk][w]: kk=2k -> ck*cos, kk=2k+1 -> -ck*sin  (c0=1, ck=2)
        int kk = t >> 9, w = t & 511, k = kk >> 1;
        int m = (w * k) & 511;
        double s, c; sincospi((double)m / 256.0, &s, &c);
        float ck = (k == 0) ? 1.f : 2.f;
        d_TI[t] = (kk & 1) ? (float)(-ck * s) : (float)(ck * c);
    }
}

// ---------------- pooling: xp[b,c,h,j] = mean_{u<8} x[..., 8j+u] ----------------
__global__ void k_pool(const float* __restrict__ x) {
    int id = blockIdx.x * 256 + threadIdx.x;    // NROW*64 exactly
    int j = id & 63;
    size_t row = (size_t)(id >> 6);
    const float* p = x + row * W_ + j * 8;
    float4 a = *(const float4*)p, b = *(const float4*)(p + 4);
    d_xp[id] = (a.x + a.y + a.z + a.w + b.x + b.y + b.z + b.w) * 0.125f;
}

// ---------------- tiled fp32 GEMM (R5 version): C[64xN128] = scale*A*B (+X) ----
template<bool ADDX>
__global__ void __launch_bounds__(256) k_gemm(
    const float* __restrict__ A, int lda,
    const float* __restrict__ Bm, int ldb,
    float* __restrict__ C, int ldc,
    const float* __restrict__ X, int K, float scale)
{
    __shared__ float As[32][65];
    __shared__ float Bs[32][128];
    const int tid = threadIdx.x;
    const int tx = tid & 15;        // cols tx + 16*v
    const int ty = tid >> 4;        // rows ty*4 + u
    const long row0 = (long)blockIdx.x * 64;
    const int col0 = blockIdx.y * 128;

    float acc[4][8];
#pragma unroll
    for (int u = 0; u < 4; u++)
#pragma unroll
        for (int v = 0; v < 8; v++) acc[u][v] = 0.f;

    for (int kc = 0; kc < K; kc += 32) {
        __syncthreads();
#pragma unroll
        for (int i = 0; i < 2; i++) {           // A tile 64x32 (transposed)
            int f = tid + i * 256;
            int r = f >> 3, q = f & 7;
            float4 v = *(const float4*)(A + (row0 + r) * lda + kc + q * 4);
            As[q * 4 + 0][r] = v.x; As[q * 4 + 1][r] = v.y;
            As[q * 4 + 2][r] = v.z; As[q * 4 + 3][r] = v.w;
        }
#pragma unroll
        for (int i = 0; i < 4; i++) {           // B tile 32x128
            int f = tid + i * 256;
            int kk = f >> 5, q = f & 31;
            *(float4*)&Bs[kk][q * 4] =
                *(const float4*)(Bm + (long)(kc + kk) * ldb + col0 + q * 4);
        }
        __syncthreads();
#pragma unroll
        for (int kk = 0; kk < 32; kk++) {
            float a[4], b[8];
#pragma unroll
            for (int u = 0; u < 4; u++) a[u] = As[kk][ty * 4 + u];
#pragma unroll
            for (int v = 0; v < 8; v++) b[v] = Bs[kk][tx + 16 * v];
#pragma unroll
            for (int u = 0; u < 4; u++)
#pragma unroll
                for (int v = 0; v < 8; v++) acc[u][v] = fmaf(a[u], b[v], acc[u][v]);
        }
    }
#pragma unroll
    for (int u = 0; u < 4; u++)
#pragma unroll
        for (int v = 0; v < 8; v++) {
            long idx = (row0 + ty * 4 + u) * ldc + col0 + tx + 16 * v;
            float val = acc[u][v] * scale;
            if (ADDX) val += X[idx];
            C[idx] = val;
        }
}

// ---------------- filter: params GEMV + nonlinearities -> G = (filt-1)/256 ------
__global__ void __launch_bounds__(256) k_filter(
    const float* __restrict__ w, const float* __restrict__ bias,
    const float* __restrict__ dt)
{
    __shared__ float ws[4096];
    __shared__ float bs[64];
    int tid = threadIdx.x;
#pragma unroll
    for (int i = tid; i < 4096; i += 256) ws[i] = w[i];
    if (tid < 64) bs[tid] = bias[tid];
    __syncthreads();

    int id = blockIdx.x * 256 + tid;            // B*H*64 = 131072
    int j = id & 63, h = (id >> 6) & 255, bb = id >> 14;
    float xv[64];
#pragma unroll
    for (int c = 0; c < 64; c++)
        xv[c] = d_xp[(((size_t)(bb * 64 + c)) * 256 + h) * 64 + j];
    float dtb = dt[bb];
    float fr = 0.f, fi = 0.f;
    for (int r = 0; r < 32; r++) {
        float p1 = bs[r], p2 = bs[32 + r];
#pragma unroll
        for (int c = 0; c < 64; c++) {
            p1 = fmaf(ws[r * 64 + c], xv[c], p1);
            p2 = fmaf(ws[(32 + r) * 64 + c], xv[c], p2);
        }
        float nu  = log1pf(expf(p1));
        float th  = tanhf(p2) * 3.14159265358979323846f;
        float dec = expf(-nu * dtb);
        float s, co; sincosf(th * dtb, &s, &co);
        fr = fmaf(dec, co, fr);
        fi = fmaf(dec, s, fi);
    }
    d_G[id] = make_float2((fr - 1.f) * 0.00390625f, fi * 0.00390625f);
}

// ---------------- fused H transform: V = IFFT_256( G .* FFT_256(U) ) ------------
// Four-step 16x16 FFT, 8 k-bins per chunk, 128 threads, one block per (b,c).
#define PSTR 9
__global__ void __launch_bounds__(128) k_hfft() {
    __shared__ float SAr[256*PSTR], SAi[256*PSTR];
    __shared__ float SBr[256*PSTR], SBi[256*PSTR];
    __shared__ float2 Ws[256];                  // W256^m (fwd sign)
    const int bc = blockIdx.x;                  // b*64 + c
    const int b = bc >> 6;
    const int t = threadIdx.x;
    const int kk = t & 7, u = t >> 3;           // u < 16

    for (int i = t; i < 256; i += 128) {
        float2 e = d_E[2 * i];
        Ws[i] = make_float2(e.x, -e.y);
    }
    const float2* Ub = (const float2*)d_U + (size_t)bc * 256 * 64;
    float2*       Vb = (float2*)d_V + (size_t)bc * 256 * 64;

    for (int kb = 0; kb < 64; kb += 8) {
        __syncthreads();                        // SA reuse vs prev chunk reads
        for (int i = t; i < 2048; i += 128) {   // load chunk (h, kk)
            int h = i >> 3, k2 = i & 7;
            float2 uv = Ub[h * 64 + kb + k2];
            SAr[h * PSTR + k2] = uv.x; SAi[h * PSTR + k2] = uv.y;
        }
        __syncthreads();
        float2 v[16];
        // phase A (fwd over n2), u = n1
#pragma unroll
        for (int n2 = 0; n2 < 16; n2++) {
            int p = (u + 16 * n2) * PSTR + kk;
            v[n2] = make_float2(SAr[p], SAi[p]);
        }
        fft16<0>(v);
#pragma unroll
        for (int k2 = 1; k2 < 16; k2++) v[k2] = cmul(v[k2], Ws[u * k2]);
#pragma unroll
        for (int k2 = 0; k2 < 16; k2++) {
            int p = (k2 * 16 + u) * PSTR + kk;
            SBr[p] = v[k2].x; SBi[p] = v[k2].y;
        }
        __syncthreads();
        // fused phase: fwd stage-2 (over n1), xG, inv stage-1 (over m2); u = k2 = m1
#pragma unroll
        for (int n1 = 0; n1 < 16; n1++) {
            int p = (u * 16 + n1) * PSTR + kk;
            v[n1] = make_float2(SBr[p], SBi[p]);
        }
        fft16<0>(v);                            // -> Xhat[k2 + 16*k1], reg idx = k1
#pragma unroll
        for (int r = 0; r < 16; r++) {
            float2 g = d_G[((size_t)b * 256 + u + 16 * r) * 64 + kb + kk];
            v[r] = cmul(v[r], g);
        }
        fft16<1>(v);                            // inverse over m2 -> Ainv[n2]
#pragma unroll
        for (int n2 = 0; n2 < 16; n2++) {
            float2 wc = Ws[u * n2]; wc.y = -wc.y;   // W256^{-m1 n2}
            float2 r = cmul(v[n2], wc);
            int p = (n2 * 16 + u) * PSTR + kk;
            SAr[p] = r.x; SAi[p] = r.y;
        }
        __syncthreads();
        // inverse stage-2 (over m1), u = n2
#pragma unroll
        for (int m1 = 0; m1 < 16; m1++) {
            int p = (u * 16 + m1) * PSTR + kk;
            v[m1] = make_float2(SAr[p], SAi[p]);
        }
        fft16<1>(v);                            // -> V[n2 + 16*n1], reg idx = n1
#pragma unroll
        for (int n1 = 0; n1 < 16; n1++)
            Vb[(u + 16 * n1) * 64 + kb + kk] = v[n1];
    }
}

// ---------------- launch ----------------
extern "C" void kernel_launch(void* const* d_in, const int* in_sizes, int n_in,
                              void* d_out, int out_size) {
    const float* x    = (const float*)d_in[0];
    const float* dt   = (const float*)d_in[1];
    const float* w    = (const float*)d_in[2];
    const float* bias = (const float*)d_in[3];
    float* out = (float*)d_out;

    void *pTF, *pTI, *pU, *pV;
    cudaGetSymbolAddress(&pTF, d_TF);
    cudaGetSymbolAddress(&pTI, d_TI);
    cudaGetSymbolAddress(&pU,  d_U);
    cudaGetSymbolAddress(&pV,  d_V);

    k_tables<<<256, 256>>>();
    k_pool<<<NROW * 64 / 256, 256>>>(x);
    // K1: U = x * TF   (131072 x 512) * (512 x 128)
    k_gemm<false><<<dim3(NROW / 64, 1), 256>>>(
        x, W_, (const float*)pTF, 128, (float*)pU, 128, nullptr, W_, 1.f);
    k_filter<<<B_ * H_ * KF / 256, 256>>>(w, bias, dt);
    // fused FFT -> xG -> IFFT along H (replaces kern/transposes/circulant)
    k_hfft<<<B_ * C_, 128>>>();
    // K5: out = x + (1/512) * V * TI   (131072 x 128) * (128 x 512)
    k_gemm<true><<<dim3(NROW / 64, 4), 256>>>(
        (const float*)pV, 128, (const float*)pTI, W_, out, W_, x, 128, 1.f / 512.f);
}

// round 8
// speedup vs baseline: 2.2799x; 1.5241x over previous
#include <cuda_runtime.h>
#include <math.h>

#define B_ 8
#define C_ 64
#define H_ 256
#define W_ 512
#define KF 64            // modified W-frequency bins
#define NROW (B_*C_*H_)  // 131072 rows

// ---------------- static device scratch (allocation-free rule) ----------------
__device__ __align__(16) float  d_TC[256 * 64];                 // cos(2pi n k/512)   [n][k]
__device__ __align__(16) float  d_TSn[256 * 64];                // -sin(2pi n k/512)  [n][k]
__device__ __align__(16) float  d_Tp[64 * 256];                 // ck*cos(2pi n k/512) [k][n]
__device__ __align__(16) float  d_Tq[64 * 256];                 // ck*sin(2pi n k/512) [k][n]
__device__ __align__(16) float2 d_E[W_];                        // e^{+2*pi*i*t/512}
__device__ __align__(16) float  d_xp[(size_t)NROW * KF];        // pooled x (b,c,h,j)
__device__ __align__(16) float2 d_G[B_ * H_ * KF];              // (filt-1)/256  (b,m,k)
__device__ __align__(16) float  d_U[(size_t)NROW * 2 * KF];     // fwd spectrum (b,c,h,k{r,i})
__device__ __align__(16) float  d_V[(size_t)NROW * 2 * KF];     // filtered (b,c,n,k{r,i})

__device__ __forceinline__ float2 cadd(float2 a, float2 b){ return make_float2(a.x+b.x, a.y+b.y); }
__device__ __forceinline__ float2 csub(float2 a, float2 b){ return make_float2(a.x-b.x, a.y-b.y); }
__device__ __forceinline__ float2 cmul(float2 a, float2 b){
    return make_float2(fmaf(a.x,b.x,-a.y*b.y), fmaf(a.x,b.y,a.y*b.x));
}

// ---------------- in-register FFT16 (natural order in/out), INV=0 fwd, 1 inv ----
template<int INV>
__device__ __forceinline__ void fft16(float2* v) {
    const float C1 = 0.9238795325112867f, S1 = 0.3826834323650898f;
    const float C2 = 0.7071067811865476f;
    const float sg = INV ? 1.f : -1.f;
    const float2 w1 = make_float2( C1, sg*S1);
    const float2 w2 = make_float2( C2, sg*C2);
    const float2 w3 = make_float2( S1, sg*C1);
    const float2 w4 = make_float2(0.f, sg);
    const float2 w6 = make_float2(-C2, sg*C2);
    const float2 w9 = make_float2(-C1, -sg*S1);
    float2 A[16];
#pragma unroll
    for (int n0 = 0; n0 < 4; n0++) {
        float2 a=v[n0], b=v[n0+4], c=v[n0+8], d=v[n0+12];
        float2 t0=cadd(a,c), t1=csub(a,c), t2=cadd(b,d), t3=csub(b,d);
        float2 jt3 = INV ? make_float2(-t3.y, t3.x) : make_float2(t3.y, -t3.x);
        A[n0*4+0]=cadd(t0,t2); A[n0*4+1]=cadd(t1,jt3);
        A[n0*4+2]=csub(t0,t2); A[n0*4+3]=csub(t1,jt3);
    }
    A[5]=cmul(A[5],w1);  A[6]=cmul(A[6],w2);  A[7]=cmul(A[7],w3);
    A[9]=cmul(A[9],w2);  A[10]=cmul(A[10],w4); A[11]=cmul(A[11],w6);
    A[13]=cmul(A[13],w3); A[14]=cmul(A[14],w6); A[15]=cmul(A[15],w9);
#pragma unroll
    for (int k1 = 0; k1 < 4; k1++) {
        float2 a=A[k1], b=A[4+k1], c=A[8+k1], d=A[12+k1];
        float2 t0=cadd(a,c), t1=csub(a,c), t2=cadd(b,d), t3=csub(b,d);
        float2 jt3 = INV ? make_float2(-t3.y, t3.x) : make_float2(t3.y, -t3.x);
        v[k1+0]=cadd(t0,t2); v[k1+4]=cadd(t1,jt3);
        v[k1+8]=csub(t0,t2); v[k1+12]=csub(t1,jt3);
    }
}

// ---------------- tables (double-precision generation) ----------------
__global__ void k_tables() {
    int t = blockIdx.x * 256 + threadIdx.x;     // 16384 threads
    if (t < 512) {
        double s, c; sincospi((double)t / 256.0, &s, &c);
        d_E[t] = make_float2((float)c, (float)s);
    }
    {   // forward: [n][k], n<256, k<64
        int n = t >> 6, k = t & 63;
        int m = (n * k) & 511;
        double s, c; sincospi((double)m / 256.0, &s, &c);
        d_TC[t]  = (float)c;
        d_TSn[t] = (float)(-s);
    }
    {   // inverse: [k][n], k<64, n<256
        int k = t >> 8, n = t & 255;
        int m = (n * k) & 511;
        double s, c; sincospi((double)m / 256.0, &s, &c);
        float ck = k ? 2.f : 1.f;
        d_Tp[t] = ck * (float)c;
        d_Tq[t] = ck * (float)s;
    }
}

// ---------------- pooling: xp[b,c,h,j] = mean_{u<8} x[..., 8j+u] ----------------
__global__ void k_pool(const float* __restrict__ x) {
    int id = blockIdx.x * 256 + threadIdx.x;    // NROW*64 exactly
    int j = id & 63;
    size_t row = (size_t)(id >> 6);
    const float* p = x + row * W_ + j * 8;
    float4 a = *(const float4*)p, b = *(const float4*)(p + 4);
    d_xp[id] = (a.x + a.y + a.z + a.w + b.x + b.y + b.z + b.w) * 0.125f;
}

// ---------------- K1 folded: U[row][2k{,+1}] from even/odd halves, K=256 --------
__global__ void __launch_bounds__(256) k_fwd(const float* __restrict__ x) {
    __shared__ float Es[32][68], Os[32][68];
    __shared__ float Tc[32][64], Tsn[32][64];
    const int tid = threadIdx.x;
    const int tx = tid & 15, ty = tid >> 4;
    const long row0 = (long)blockIdx.x * 64;

    float aR[4][4], aI[4][4];
#pragma unroll
    for (int u = 0; u < 4; u++)
#pragma unroll
        for (int w = 0; w < 4; w++) { aR[u][w] = 0.f; aI[u][w] = 0.f; }

    for (int kc = 0; kc < 256; kc += 32) {
        __syncthreads();
        // A fold: E[n]=x[n]+x[512-n] (E[0]=x[0]), O[n]=x[n]-x[512-n]
#pragma unroll
        for (int i = 0; i < 2; i++) {
            int f = tid + i * 256;          // 512 slots
            int r = f >> 3, qg = f & 7;
            const float* xp = x + (row0 + r) * W_;
            int n0 = kc + qg * 4;
            float4 fw = *(const float4*)(xp + n0);
            float rv0 = (n0 == 0) ? 0.f : xp[512 - n0];
            float rv1 = xp[511 - n0];
            float rv2 = xp[510 - n0];
            float rv3 = xp[509 - n0];
            Es[qg*4+0][r] = fw.x + rv0; Os[qg*4+0][r] = fw.x - rv0;
            Es[qg*4+1][r] = fw.y + rv1; Os[qg*4+1][r] = fw.y - rv1;
            Es[qg*4+2][r] = fw.z + rv2; Os[qg*4+2][r] = fw.z - rv2;
            Es[qg*4+3][r] = fw.w + rv3; Os[qg*4+3][r] = fw.w - rv3;
        }
        // B tiles: TC/TSn 32x64 each
#pragma unroll
        for (int i = 0; i < 4; i++) {
            int f = tid + i * 256;          // 1024 float4 slots
            int which = f >> 9, g = f & 511;
            int q = g >> 4, c4 = (g & 15) * 4;
            float4 v = *(const float4*)((which ? d_TSn : d_TC) + (kc + q) * 64 + c4);
            *(float4*)(which ? &Tsn[q][c4] : &Tc[q][c4]) = v;
        }
        __syncthreads();
#pragma unroll
        for (int kk = 0; kk < 32; kk++) {
            float4 e4 = *(const float4*)&Es[kk][ty * 4];
            float4 o4 = *(const float4*)&Os[kk][ty * 4];
            float4 c4 = *(const float4*)&Tc[kk][tx * 4];
            float4 s4 = *(const float4*)&Tsn[kk][tx * 4];
            float eu[4] = {e4.x, e4.y, e4.z, e4.w};
            float ou[4] = {o4.x, o4.y, o4.z, o4.w};
            float bc[4] = {c4.x, c4.y, c4.z, c4.w};
            float bs[4] = {s4.x, s4.y, s4.z, s4.w};
#pragma unroll
            for (int u = 0; u < 4; u++)
#pragma unroll
                for (int w = 0; w < 4; w++) {
                    aR[u][w] = fmaf(eu[u], bc[w], aR[u][w]);
                    aI[u][w] = fmaf(ou[u], bs[w], aI[u][w]);
                }
        }
    }
    // epilogue: += x[256]*(-1)^k on the real part; store interleaved
#pragma unroll
    for (int u = 0; u < 4; u++) {
        long row = row0 + ty * 4 + u;
        float xr = x[row * W_ + 256];
        float* Up = d_U + row * 128 + tx * 8;       // k = tx*4 + w
        float4 o0 = make_float4(aR[u][0] + xr, aI[u][0], aR[u][1] - xr, aI[u][1]);
        float4 o1 = make_float4(aR[u][2] + xr, aI[u][2], aR[u][3] - xr, aI[u][3]);
        *(float4*)Up = o0;
        *(float4*)(Up + 4) = o1;
    }
}

// ---------------- filter: params GEMV + nonlinearities -> G = (filt-1)/256 ------
__global__ void __launch_bounds__(256) k_filter(
    const float* __restrict__ w, const float* __restrict__ bias,
    const float* __restrict__ dt)
{
    __shared__ float ws[4096];
    __shared__ float bs[64];
    int tid = threadIdx.x;
#pragma unroll
    for (int i = tid; i < 4096; i += 256) ws[i] = w[i];
    if (tid < 64) bs[tid] = bias[tid];
    __syncthreads();

    int id = blockIdx.x * 256 + tid;            // B*H*64 = 131072
    int j = id & 63, h = (id >> 6) & 255, bb = id >> 14;
    float xv[64];
#pragma unroll
    for (int c = 0; c < 64; c++)
        xv[c] = d_xp[(((size_t)(bb * 64 + c)) * 256 + h) * 64 + j];
    float dtb = dt[bb];
    float fr = 0.f, fi = 0.f;
    for (int r = 0; r < 32; r++) {
        float p1 = bs[r], p2 = bs[32 + r];
#pragma unroll
        for (int c = 0; c < 64; c++) {
            p1 = fmaf(ws[r * 64 + c], xv[c], p1);
            p2 = fmaf(ws[(32 + r) * 64 + c], xv[c], p2);
        }
        float nu  = log1pf(expf(p1));
        float th  = tanhf(p2) * 3.14159265358979323846f;
        float dec = expf(-nu * dtb);
        float s, co; sincosf(th * dtb, &s, &co);
        fr = fmaf(dec, co, fr);
        fi = fmaf(dec, s, fi);
    }
    d_G[id] = make_float2((fr - 1.f) * 0.00390625f, fi * 0.00390625f);
}

// ---------------- fused H transform: V = IFFT_256( G .* FFT_256(U) ) ------------
#define PSTR 9
__global__ void __launch_bounds__(128) k_hfft() {
    __shared__ float SAr[256*PSTR], SAi[256*PSTR];
    __shared__ float SBr[256*PSTR], SBi[256*PSTR];
    __shared__ float2 Ws[256];
    const int bc = blockIdx.x;                  // b*64 + c
    const int b = bc >> 6;
    const int t = threadIdx.x;
    const int kk = t & 7, u = t >> 3;

    for (int i = t; i < 256; i += 128) {
        float2 e = d_E[2 * i];
        Ws[i] = make_float2(e.x, -e.y);
    }
    const float2* Ub = (const float2*)d_U + (size_t)bc * 256 * 64;
    float2*       Vb = (float2*)d_V + (size_t)bc * 256 * 64;

    for (int kb = 0; kb < 64; kb += 8) {
        __syncthreads();
        for (int i = t; i < 2048; i += 128) {
            int h = i >> 3, k2 = i & 7;
            float2 uv = Ub[h * 64 + kb + k2];
            SAr[h * PSTR + k2] = uv.x; SAi[h * PSTR + k2] = uv.y;
        }
        __syncthreads();
        float2 v[16];
#pragma unroll
        for (int n2 = 0; n2 < 16; n2++) {
            int p = (u + 16 * n2) * PSTR + kk;
            v[n2] = make_float2(SAr[p], SAi[p]);
        }
        fft16<0>(v);
#pragma unroll
        for (int k2 = 1; k2 < 16; k2++) v[k2] = cmul(v[k2], Ws[u * k2]);
#pragma unroll
        for (int k2 = 0; k2 < 16; k2++) {
            int p = (k2 * 16 + u) * PSTR + kk;
            SBr[p] = v[k2].x; SBi[p] = v[k2].y;
        }
        __syncthreads();
#pragma unroll
        for (int n1 = 0; n1 < 16; n1++) {
            int p = (u * 16 + n1) * PSTR + kk;
            v[n1] = make_float2(SBr[p], SBi[p]);
        }
        fft16<0>(v);
#pragma unroll
        for (int r = 0; r < 16; r++) {
            float2 g = d_G[((size_t)b * 256 + u + 16 * r) * 64 + kb + kk];
            v[r] = cmul(v[r], g);
        }
        fft16<1>(v);
#pragma unroll
        for (int n2 = 0; n2 < 16; n2++) {
            float2 wc = Ws[u * n2]; wc.y = -wc.y;
            float2 r = cmul(v[n2], wc);
            int p = (n2 * 16 + u) * PSTR + kk;
            SAr[p] = r.x; SAi[p] = r.y;
        }
        __syncthreads();
#pragma unroll
        for (int m1 = 0; m1 < 16; m1++) {
            int p = (u * 16 + m1) * PSTR + kk;
            v[m1] = make_float2(SAr[p], SAi[p]);
        }
        fft16<1>(v);
#pragma unroll
        for (int n1 = 0; n1 < 16; n1++)
            Vb[(u + 16 * n1) * 64 + kb + kk] = v[n1];
    }
}

// ---------------- K5 folded: out[n]=x[n]+s(P-Q), out[512-n]=x[512-n]+s(P+Q) ------
__global__ void __launch_bounds__(256) k_inv(const float* __restrict__ x,
                                             float* __restrict__ out) {
    __shared__ float As[32][68];
    __shared__ float Bp[16][64], Bq[16][64];
    const int tid = threadIdx.x;
    const int tx = tid & 15, ty = tid >> 4;
    const long row0 = (long)blockIdx.x * 64;
    const int nb = blockIdx.y * 64;             // n in [nb, nb+64), nb<256

    float P[4][4], Q[4][4];
#pragma unroll
    for (int u = 0; u < 4; u++)
#pragma unroll
        for (int w = 0; w < 4; w++) { P[u][w] = 0.f; Q[u][w] = 0.f; }

    for (int kc = 0; kc < 128; kc += 32) {
        __syncthreads();
#pragma unroll
        for (int i = 0; i < 2; i++) {
            int f = tid + i * 256;
            int r = f >> 3, qg = f & 7;
            float4 v = *(const float4*)(d_V + (row0 + r) * 128 + kc + qg * 4);
            As[qg*4+0][r] = v.x; As[qg*4+1][r] = v.y;
            As[qg*4+2][r] = v.z; As[qg*4+3][r] = v.w;
        }
#pragma unroll
        for (int i = 0; i < 2; i++) {
            int f = tid + i * 256;              // 512 float4 over both tables
            int which = f >> 8, g = f & 255;
            int kl = g >> 4, c4 = (g & 15) * 4;
            float4 v = *(const float4*)((which ? d_Tq : d_Tp)
                        + ((kc >> 1) + kl) * 256 + nb + c4);
            *(float4*)(which ? &Bq[kl][c4] : &Bp[kl][c4]) = v;
        }
        __syncthreads();
#pragma unroll
        for (int kl = 0; kl < 16; kl++) {
            float4 ap4 = *(const float4*)&As[2*kl][ty * 4];
            float4 aq4 = *(const float4*)&As[2*kl+1][ty * 4];
            float4 bp4 = *(const float4*)&Bp[kl][tx * 4];
            float4 bq4 = *(const float4*)&Bq[kl][tx * 4];
            float ap[4] = {ap4.x, ap4.y, ap4.z, ap4.w};
            float aq[4] = {aq4.x, aq4.y, aq4.z, aq4.w};
            float bp[4] = {bp4.x, bp4.y, bp4.z, bp4.w};
            float bq[4] = {bq4.x, bq4.y, bq4.z, bq4.w};
#pragma unroll
            for (int u = 0; u < 4; u++)
#pragma unroll
                for (int w = 0; w < 4; w++) {
                    P[u][w] = fmaf(ap[u], bp[w], P[u][w]);
                    Q[u][w] = fmaf(aq[u], bq[w], Q[u][w]);
                }
        }
    }
    const float s = 1.f / 512.f;
#pragma unroll
    for (int u = 0; u < 4; u++) {
        long row = row0 + ty * 4 + u;
        const float* xr = x + row * W_;
        float* orow = out + row * W_;
        int n0 = nb + tx * 4;
        float4 xf = *(const float4*)(xr + n0);
        float4 o1;
        o1.x = fmaf(P[u][0] - Q[u][0], s, xf.x);
        o1.y = fmaf(P[u][1] - Q[u][1], s, xf.y);
        o1.z = fmaf(P[u][2] - Q[u][2], s, xf.z);
        o1.w = fmaf(P[u][3] - Q[u][3], s, xf.w);
        *(float4*)(orow + n0) = o1;
#pragma unroll
        for (int w = 0; w < 4; w++) {
            int n2 = (512 - (n0 + w)) & 511;
            orow[n2] = fmaf(P[u][w] + Q[u][w], s, xr[n2]);
        }
    }
}

// ---------------- column 256: out[row][256] = x + s * sum ck*(-1)^k*Vr[k] --------
__global__ void k_c256(const float* __restrict__ x, float* __restrict__ out) {
    int tid = threadIdx.x;
    int lane = tid & 31, rl = tid >> 5;
    long row = (long)blockIdx.x * 8 + rl;
    const float* vp = d_V + row * 128;
    float w1 = (lane == 0 ? 1.f : 2.f) * ((lane & 1) ? -1.f : 1.f);
    float w2 = 2.f * (((lane + 32) & 1) ? -1.f : 1.f);
    float sum = vp[2 * lane] * w1 + vp[2 * (lane + 32)] * w2;
#pragma unroll
    for (int o = 16; o > 0; o >>= 1) sum += __shfl_down_sync(0xffffffffu, sum, o);
    if (lane == 0)
        out[row * W_ + 256] = fmaf(sum, 1.f / 512.f, x[row * W_ + 256]);
}

// ---------------- launch ----------------
extern "C" void kernel_launch(void* const* d_in, const int* in_sizes, int n_in,
                              void* d_out, int out_size) {
    const float* x    = (const float*)d_in[0];
    const float* dt   = (const float*)d_in[1];
    const float* w    = (const float*)d_in[2];
    const float* bias = (const float*)d_in[3];
    float* out = (float*)d_out;

    k_tables<<<64, 256>>>();
    k_pool<<<NROW * 64 / 256, 256>>>(x);
    k_fwd<<<NROW / 64, 256>>>(x);
    k_filter<<<B_ * H_ * KF / 256, 256>>>(w, bias, dt);
    k_hfft<<<B_ * C_, 128>>>();
    k_inv<<<dim3(NROW / 64, 4), 256>>>(x, out);
    k_c256<<<NROW / 8, 256>>>(x, out);
}

// round 9
// speedup vs baseline: 2.6479x; 1.1614x over previous
#include <cuda_runtime.h>
#include <math.h>

#define B_ 8
#define C_ 64
#define H_ 256
#define W_ 512
#define KF 64
#define NROW (B_*C_*H_)  // 131072 rows

// ---------------- static device scratch (allocation-free rule) ----------------
__device__ __align__(16) float  d_Tce[128 * 32];   // cos(2pi n j/256)        [n][j]
__device__ __align__(16) float  d_Tco[128 * 32];   // cos(pi n (2j+1)/256)    [n][j]
__device__ __align__(16) float  d_Tse[128 * 32];   // -sin(2pi n j/256)       [n][j]
__device__ __align__(16) float  d_Tso[128 * 32];   // -sin(pi n (2j+1)/256)   [n][j]
__device__ __align__(16) float  d_Ipe[32 * 128];   // c2j cos(2pi n j/256)    [j][n]
__device__ __align__(16) float  d_Ipo[32 * 128];   // 2 cos(pi n (2j+1)/256)  [j][n]
__device__ __align__(16) float  d_Iqe[32 * 128];   // c2j sin(2pi n j/256)    [j][n]
__device__ __align__(16) float  d_Iqo[32 * 128];   // 2 sin(pi n (2j+1)/256)  [j][n]
__device__ __align__(16) float2 d_E[W_];           // e^{+2 pi i t/512}
__device__ __align__(16) float  d_xp[(size_t)NROW * KF];
__device__ __align__(16) float2 d_G[B_ * H_ * KF];           // (filt-1)/256
__device__ __align__(16) float  d_U[(size_t)NROW * 2 * KF];  // (b,c,h,k{r,i})
__device__ __align__(16) float  d_V[(size_t)NROW * 2 * KF];  // (b,c,n,k{r,i})

__device__ __forceinline__ float2 cadd(float2 a, float2 b){ return make_float2(a.x+b.x, a.y+b.y); }
__device__ __forceinline__ float2 csub(float2 a, float2 b){ return make_float2(a.x-b.x, a.y-b.y); }
__device__ __forceinline__ float2 cmul(float2 a, float2 b){
    return make_float2(fmaf(a.x,b.x,-a.y*b.y), fmaf(a.x,b.y,a.y*b.x));
}

// ---------------- in-register FFT16 (natural order), INV=0 fwd, 1 inv ----------
template<int INV>
__device__ __forceinline__ void fft16(float2* v) {
    const float C1 = 0.9238795325112867f, S1 = 0.3826834323650898f;
    const float C2 = 0.7071067811865476f;
    const float sg = INV ? 1.f : -1.f;
    const float2 w1 = make_float2( C1, sg*S1);
    const float2 w2 = make_float2( C2, sg*C2);
    const float2 w3 = make_float2( S1, sg*C1);
    const float2 w4 = make_float2(0.f, sg);
    const float2 w6 = make_float2(-C2, sg*C2);
    const float2 w9 = make_float2(-C1, -sg*S1);
    float2 A[16];
#pragma unroll
    for (int n0 = 0; n0 < 4; n0++) {
        float2 a=v[n0], b=v[n0+4], c=v[n0+8], d=v[n0+12];
        float2 t0=cadd(a,c), t1=csub(a,c), t2=cadd(b,d), t3=csub(b,d);
        float2 jt3 = INV ? make_float2(-t3.y, t3.x) : make_float2(t3.y, -t3.x);
        A[n0*4+0]=cadd(t0,t2); A[n0*4+1]=cadd(t1,jt3);
        A[n0*4+2]=csub(t0,t2); A[n0*4+3]=csub(t1,jt3);
    }
    A[5]=cmul(A[5],w1);  A[6]=cmul(A[6],w2);  A[7]=cmul(A[7],w3);
    A[9]=cmul(A[9],w2);  A[10]=cmul(A[10],w4); A[11]=cmul(A[11],w6);
    A[13]=cmul(A[13],w3); A[14]=cmul(A[14],w6); A[15]=cmul(A[15],w9);
#pragma unroll
    for (int k1 = 0; k1 < 4; k1++) {
        float2 a=A[k1], b=A[4+k1], c=A[8+k1], d=A[12+k1];
        float2 t0=cadd(a,c), t1=csub(a,c), t2=cadd(b,d), t3=csub(b,d);
        float2 jt3 = INV ? make_float2(-t3.y, t3.x) : make_float2(t3.y, -t3.x);
        v[k1+0]=cadd(t0,t2); v[k1+4]=cadd(t1,jt3);
        v[k1+8]=csub(t0,t2); v[k1+12]=csub(t1,jt3);
    }
}

// ---------------- tables ----------------
__global__ void k_tables() {
    int t = blockIdx.x * 256 + threadIdx.x;     // 32768
    if (t < 512) {
        double s, c; sincospi((double)t / 256.0, &s, &c);
        d_E[t] = make_float2((float)c, (float)s);
    }
    int id = t >> 12, idx = t & 4095;
    double s, c;
    if (id < 4) {                               // fwd: idx = n*32 + j
        int n = idx >> 5, j = idx & 31;
        if (id == 0 || id == 2) sincospi((double)(n * j) / 128.0, &s, &c);
        else                    sincospi((double)(n * (2 * j + 1)) / 256.0, &s, &c);
        if (id == 0) d_Tce[idx] = (float)c;
        else if (id == 1) d_Tco[idx] = (float)c;
        else if (id == 2) d_Tse[idx] = (float)(-s);
        else              d_Tso[idx] = (float)(-s);
    } else {                                    // inv: idx = j*128 + n
        int j = idx >> 7, n = idx & 127;
        if (id == 4 || id == 6) sincospi((double)(n * j) / 128.0, &s, &c);
        else                    sincospi((double)(n * (2 * j + 1)) / 256.0, &s, &c);
        float ce = (j == 0) ? 1.f : 2.f;
        if (id == 4) d_Ipe[idx] = ce * (float)c;
        else if (id == 5) d_Ipo[idx] = 2.f * (float)c;
        else if (id == 6) d_Iqe[idx] = ce * (float)s;
        else              d_Iqo[idx] = 2.f * (float)s;
    }
}

// ---------------- pooling ----------------
__global__ void k_pool(const float* __restrict__ x) {
    int id = blockIdx.x * 256 + threadIdx.x;
    int j = id & 63;
    size_t row = (size_t)(id >> 6);
    const float* p = x + row * W_ + j * 8;
    float4 a = *(const float4*)p, b = *(const float4*)(p + 4);
    d_xp[id] = (a.x + a.y + a.z + a.w + b.x + b.y + b.z + b.w) * 0.125f;
}

// ---------------- K1 double-folded forward: K=128, 4 planes ----------------
__global__ void __launch_bounds__(256) k_fwd(const float* __restrict__ x) {
    __shared__ float SEp[16][68], SEm[16][68], SOm[16][68], SOp[16][68];
    __shared__ float SCe[16][32], SCo[16][32], SSe[16][32], SSo[16][32];
    const int tid = threadIdx.x;
    const int tx = tid & 15, ty = tid >> 4;
    const long row0 = (long)blockIdx.x * 64;

    float re_e[4][2], re_o[4][2], im_e[4][2], im_o[4][2];
#pragma unroll
    for (int u = 0; u < 4; u++)
#pragma unroll
        for (int p = 0; p < 2; p++) {
            re_e[u][p] = 0.f; re_o[u][p] = 0.f;
            im_e[u][p] = 0.f; im_o[u][p] = 0.f;
        }

    for (int kc = 0; kc < 128; kc += 16) {
        __syncthreads();
        {   // A planes: r = tid>>2 rows, qg = tid&3 -> 4 n's each
            int r = tid >> 2, qg = tid & 3;
            int n0 = kc + qg * 4;
            const float* xp = x + (row0 + r) * W_;
            float4 fw = *(const float4*)(xp + n0);
            float xa[4] = {fw.x, fw.y, fw.z, fw.w};
#pragma unroll
            for (int q = 0; q < 4; q++) {
                int n = n0 + q;
                float xb = xp[256 - n];
                float xc = xp[256 + n];
                float xd = xp[(512 - n) & 511];
                float sa = xa[q] + xd, da = xa[q] - xd;
                float sb = xb + xc,   db = xb - xc;
                float ep = sa + sb, em = sa - sb, om = da - db, op = da + db;
                if (n == 0) { ep = 0.f; em = 0.f; om = 0.f; op = 0.f; }
                int nl = qg * 4 + q;
                SEp[nl][r] = ep; SEm[nl][r] = em;
                SOm[nl][r] = om; SOp[nl][r] = op;
            }
        }
#pragma unroll
        for (int i = 0; i < 2; i++) {           // B tiles
            int f = tid + i * 256;
            int which = f >> 7, g = f & 127;
            int nl = g >> 3, c4 = (g & 7) * 4;
            const float* src =
                (which == 0 ? d_Tce : which == 1 ? d_Tco : which == 2 ? d_Tse : d_Tso)
                + (kc + nl) * 32 + c4;
            float4 v = *(const float4*)src;
            float* dst = (which == 0 ? &SCe[nl][c4] : which == 1 ? &SCo[nl][c4]
                        : which == 2 ? &SSe[nl][c4] : &SSo[nl][c4]);
            *(float4*)dst = v;
        }
        __syncthreads();
#pragma unroll
        for (int nl = 0; nl < 16; nl++) {
            float4 ep4 = *(const float4*)&SEp[nl][ty * 4];
            float4 em4 = *(const float4*)&SEm[nl][ty * 4];
            float4 om4 = *(const float4*)&SOm[nl][ty * 4];
            float4 op4 = *(const float4*)&SOp[nl][ty * 4];
            float2 ce = *(const float2*)&SCe[nl][tx * 2];
            float2 co = *(const float2*)&SCo[nl][tx * 2];
            float2 se = *(const float2*)&SSe[nl][tx * 2];
            float2 so = *(const float2*)&SSo[nl][tx * 2];
            float ep[4] = {ep4.x, ep4.y, ep4.z, ep4.w};
            float em[4] = {em4.x, em4.y, em4.z, em4.w};
            float om[4] = {om4.x, om4.y, om4.z, om4.w};
            float op[4] = {op4.x, op4.y, op4.z, op4.w};
            float cev[2] = {ce.x, ce.y}, cov[2] = {co.x, co.y};
            float sev[2] = {se.x, se.y}, sov[2] = {so.x, so.y};
#pragma unroll
            for (int u = 0; u < 4; u++)
#pragma unroll
                for (int p = 0; p < 2; p++) {
                    re_e[u][p] = fmaf(ep[u], cev[p], re_e[u][p]);
                    re_o[u][p] = fmaf(em[u], cov[p], re_o[u][p]);
                    im_e[u][p] = fmaf(om[u], sev[p], im_e[u][p]);
                    im_o[u][p] = fmaf(op[u], sov[p], im_o[u][p]);
                }
        }
    }
    // epilogue: boundary terms x[0], x[128], x[256], x[384]
#pragma unroll
    for (int u = 0; u < 4; u++) {
        long row = row0 + ty * 4 + u;
        const float* xp = x + row * W_;
        float x0 = xp[0], x128 = xp[128], x256 = xp[256], x384 = xp[384];
        float e128 = x128 + x384, o128 = x128 - x384;
        float* Up = d_U + row * 128 + tx * 8;
        float4 a, b;
        a.x = re_e[u][0] + x0 + e128 + x256;    // k=4tx   re
        a.y = im_e[u][0];                       //         im
        a.z = re_o[u][0] + x0 - x256;           // k=4tx+1 re
        a.w = im_o[u][0] - o128;                //         im
        b.x = re_e[u][1] + x0 - e128 + x256;    // k=4tx+2 re
        b.y = im_e[u][1];
        b.z = re_o[u][1] + x0 - x256;           // k=4tx+3 re
        b.w = im_o[u][1] + o128;
        *(float4*)Up = a;
        *(float4*)(Up + 4) = b;
    }
}

// ---------------- filter ----------------
__global__ void __launch_bounds__(256) k_filter(
    const float* __restrict__ w, const float* __restrict__ bias,
    const float* __restrict__ dt)
{
    __shared__ float ws[4096];
    __shared__ float bs[64];
    int tid = threadIdx.x;
#pragma unroll
    for (int i = tid; i < 4096; i += 256) ws[i] = w[i];
    if (tid < 64) bs[tid] = bias[tid];
    __syncthreads();

    int id = blockIdx.x * 256 + tid;
    int j = id & 63, h = (id >> 6) & 255, bb = id >> 14;
    float xv[64];
#pragma unroll
    for (int c = 0; c < 64; c++)
        xv[c] = d_xp[(((size_t)(bb * 64 + c)) * 256 + h) * 64 + j];
    float dtb = dt[bb];
    float fr = 0.f, fi = 0.f;
    for (int r = 0; r < 32; r++) {
        float p1 = bs[r], p2 = bs[32 + r];
#pragma unroll
        for (int c = 0; c < 64; c++) {
            p1 = fmaf(ws[r * 64 + c], xv[c], p1);
            p2 = fmaf(ws[(32 + r) * 64 + c], xv[c], p2);
        }
        float nu  = log1pf(expf(p1));
        float th  = tanhf(p2) * 3.14159265358979323846f;
        float dec = expf(-nu * dtb);
        float s, co; sincosf(th * dtb, &s, &co);
        fr = fmaf(dec, co, fr);
        fi = fmaf(dec, s, fi);
    }
    d_G[id] = make_float2((fr - 1.f) * 0.00390625f, fi * 0.00390625f);
}

// ---------------- fused H transform: V = IFFT_256( G .* FFT_256(U) ) ------------
#define PSTR 9
__global__ void __launch_bounds__(128) k_hfft() {
    __shared__ float SAr[256*PSTR], SAi[256*PSTR];
    __shared__ float SBr[256*PSTR], SBi[256*PSTR];
    __shared__ float2 Ws[256];
    const int bc = blockIdx.x;
    const int b = bc >> 6;
    const int t = threadIdx.x;
    const int kk = t & 7, u = t >> 3;

    for (int i = t; i < 256; i += 128) {
        float2 e = d_E[2 * i];
        Ws[i] = make_float2(e.x, -e.y);
    }
    const float2* Ub = (const float2*)d_U + (size_t)bc * 256 * 64;
    float2*       Vb = (float2*)d_V + (size_t)bc * 256 * 64;

    for (int kb = 0; kb < 64; kb += 8) {
        __syncthreads();
        for (int i = t; i < 2048; i += 128) {
            int h = i >> 3, k2 = i & 7;
            float2 uv = Ub[h * 64 + kb + k2];
            SAr[h * PSTR + k2] = uv.x; SAi[h * PSTR + k2] = uv.y;
        }
        __syncthreads();
        float2 v[16];
#pragma unroll
        for (int n2 = 0; n2 < 16; n2++) {
            int p = (u + 16 * n2) * PSTR + kk;
            v[n2] = make_float2(SAr[p], SAi[p]);
        }
        fft16<0>(v);
#pragma unroll
        for (int k2 = 1; k2 < 16; k2++) v[k2] = cmul(v[k2], Ws[u * k2]);
#pragma unroll
        for (int k2 = 0; k2 < 16; k2++) {
            int p = (k2 * 16 + u) * PSTR + kk;
            SBr[p] = v[k2].x; SBi[p] = v[k2].y;
        }
        __syncthreads();
#pragma unroll
        for (int n1 = 0; n1 < 16; n1++) {
            int p = (u * 16 + n1) * PSTR + kk;
            v[n1] = make_float2(SBr[p], SBi[p]);
        }
        fft16<0>(v);
#pragma unroll
        for (int r = 0; r < 16; r++) {
            float2 g = d_G[((size_t)b * 256 + u + 16 * r) * 64 + kb + kk];
            v[r] = cmul(v[r], g);
        }
        fft16<1>(v);
#pragma unroll
        for (int n2 = 0; n2 < 16; n2++) {
            float2 wc = Ws[u * n2]; wc.y = -wc.y;
            float2 r = cmul(v[n2], wc);
            int p = (n2 * 16 + u) * PSTR + kk;
            SAr[p] = r.x; SAi[p] = r.y;
        }
        __syncthreads();
#pragma unroll
        for (int m1 = 0; m1 < 16; m1++) {
            int p = (u * 16 + m1) * PSTR + kk;
            v[m1] = make_float2(SAr[p], SAi[p]);
        }
        fft16<1>(v);
#pragma unroll
        for (int n1 = 0; n1 < 16; n1++)
            Vb[(u + 16 * n1) * 64 + kb + kk] = v[n1];
    }
}

// ---------------- K5 double-folded inverse: 4 accums -> 4 output columns --------
__global__ void __launch_bounds__(256) k_inv(const float* __restrict__ x,
                                             float* __restrict__ out) {
    __shared__ float4 AV[16][65];
    __shared__ float SPe[16][64], SPo[16][64], SQe[16][64], SQo[16][64];
    const int tid = threadIdx.x;
    const int tx = tid & 15, ty = tid >> 4;
    const long row0 = (long)blockIdx.x * 64;
    const int n0 = blockIdx.y * 64;             // n in [n0, n0+64), n0 in {0,64}

    float Pe[4][4], Po[4][4], Qe[4][4], Qo[4][4];
#pragma unroll
    for (int u = 0; u < 4; u++)
#pragma unroll
        for (int w = 0; w < 4; w++) { Pe[u][w]=0.f; Po[u][w]=0.f; Qe[u][w]=0.f; Qo[u][w]=0.f; }

    for (int jc = 0; jc < 32; jc += 16) {
        __syncthreads();
#pragma unroll
        for (int i = 0; i < 4; i++) {           // V: float4 per (row, j)
            int f = tid + i * 256;
            int r = f >> 4, jl = f & 15;
            AV[jl][r] = *(const float4*)&d_V[(row0 + r) * 128 + (jc + jl) * 4];
        }
#pragma unroll
        for (int i = 0; i < 4; i++) {           // B tables
            int f = tid + i * 256;
            int which = f >> 8, g = f & 255;
            int jl = g >> 4, n4 = (g & 15) * 4;
            const float* src =
                (which == 0 ? d_Ipe : which == 1 ? d_Ipo : which == 2 ? d_Iqe : d_Iqo)
                + (jc + jl) * 128 + n0 + n4;
            float* dst = (which == 0 ? &SPe[jl][n4] : which == 1 ? &SPo[jl][n4]
                        : which == 2 ? &SQe[jl][n4] : &SQo[jl][n4]);
            *(float4*)dst = *(const float4*)src;
        }
        __syncthreads();
#pragma unroll
        for (int jl = 0; jl < 16; jl++) {
            float4 av[4];
#pragma unroll
            for (int u = 0; u < 4; u++) av[u] = AV[jl][ty * 4 + u];
            float4 pe4 = *(const float4*)&SPe[jl][tx * 4];
            float4 po4 = *(const float4*)&SPo[jl][tx * 4];
            float4 qe4 = *(const float4*)&SQe[jl][tx * 4];
            float4 qo4 = *(const float4*)&SQo[jl][tx * 4];
            float pe[4] = {pe4.x, pe4.y, pe4.z, pe4.w};
            float po[4] = {po4.x, po4.y, po4.z, po4.w};
            float qe[4] = {qe4.x, qe4.y, qe4.z, qe4.w};
            float qo[4] = {qo4.x, qo4.y, qo4.z, qo4.w};
#pragma unroll
            for (int u = 0; u < 4; u++)
#pragma unroll
                for (int w = 0; w < 4; w++) {
                    Pe[u][w] = fmaf(av[u].x, pe[w], Pe[u][w]);
                    Qe[u][w] = fmaf(av[u].y, qe[w], Qe[u][w]);
                    Po[u][w] = fmaf(av[u].z, po[w], Po[u][w]);
                    Qo[u][w] = fmaf(av[u].w, qo[w], Qo[u][w]);
                }
        }
    }
    const float s = 1.f / 512.f;
#pragma unroll
    for (int u = 0; u < 4; u++) {
        long row = row0 + ty * 4 + u;
        const float* xr = x + row * W_;
        float* orow = out + row * W_;
        int nn0 = n0 + tx * 4;
        float4 xf = *(const float4*)(xr + nn0);
        float4 xg = *(const float4*)(xr + 256 + nn0);
        float4 o1, o2;
        float d1[4], d2[4], d3[4], d4[4];
#pragma unroll
        for (int w = 0; w < 4; w++) {
            float pp = Pe[u][w] + Po[u][w], pm = Pe[u][w] - Po[u][w];
            float qp = Qe[u][w] + Qo[u][w], qm = Qe[u][w] - Qo[u][w];
            d1[w] = pp - qp;    // y[n]
            d2[w] = pp + qp;    // y[512-n]
            d3[w] = pm + qm;    // y[256-n]
            d4[w] = pm - qm;    // y[256+n]
        }
        o1.x = fmaf(d1[0], s, xf.x); o1.y = fmaf(d1[1], s, xf.y);
        o1.z = fmaf(d1[2], s, xf.z); o1.w = fmaf(d1[3], s, xf.w);
        o2.x = fmaf(d4[0], s, xg.x); o2.y = fmaf(d4[1], s, xg.y);
        o2.z = fmaf(d4[2], s, xg.z); o2.w = fmaf(d4[3], s, xg.w);
        *(float4*)(orow + nn0) = o1;
        *(float4*)(orow + 256 + nn0) = o2;
#pragma unroll
        for (int w = 0; w < 4; w++) {
            int i2 = (512 - (nn0 + w)) & 511;
            orow[i2] = fmaf(d2[w], s, xr[i2]);
            int i3 = 256 - (nn0 + w);
            orow[i3] = fmaf(d3[w], s, xr[i3]);
        }
    }
}

// ---------------- edge columns 128 & 384 ----------------
__global__ void k_edge(const float* __restrict__ x, float* __restrict__ out) {
    int tid = threadIdx.x;
    int lane = tid & 31, wr = tid >> 5;
    long row = (long)blockIdx.x * 8 + wr;
    float4 v = *(const float4*)&d_V[row * 128 + lane * 4];
    float sg = (lane & 1) ? -1.f : 1.f;
    float pe = ((lane == 0) ? 1.f : 2.f) * sg * v.x;
    float qo = 2.f * sg * v.w;
#pragma unroll
    for (int o = 16; o > 0; o >>= 1) {
        pe += __shfl_down_sync(0xffffffffu, pe, o);
        qo += __shfl_down_sync(0xffffffffu, qo, o);
    }
    if (lane == 0) {
        const float s = 1.f / 512.f;
        out[row * W_ + 128] = fmaf(pe - qo, s, x[row * W_ + 128]);
        out[row * W_ + 384] = fmaf(pe + qo, s, x[row * W_ + 384]);
    }
}

// ---------------- launch ----------------
extern "C" void kernel_launch(void* const* d_in, const int* in_sizes, int n_in,
                              void* d_out, int out_size) {
    const float* x    = (const float*)d_in[0];
    const float* dt   = (const float*)d_in[1];
    const float* w    = (const float*)d_in[2];
    const float* bias = (const float*)d_in[3];
    float* out = (float*)d_out;

    k_tables<<<128, 256>>>();
    k_pool<<<NROW * 64 / 256, 256>>>(x);
    k_fwd<<<NROW / 64, 256>>>(x);
    k_filter<<<B_ * H_ * KF / 256, 256>>>(w, bias, dt);
    k_hfft<<<B_ * C_, 128>>>();
    k_inv<<<dim3(NROW / 64, 2), 256>>>(x, out);
    k_edge<<<NROW / 8, 256>>>(x, out);
}

// round 10
// speedup vs baseline: 2.7179x; 1.0264x over previous
#include <cuda_runtime.h>
#include <math.h>

#define B_ 8
#define C_ 64
#define H_ 256
#define W_ 512
#define KF 64
#define NROW (B_*C_*H_)  // 131072 rows

// ---------------- static device scratch (allocation-free rule) ----------------
__device__ __align__(16) float  d_Tce[128 * 32];   // cos(2pi n j/256)        [n][j]
__device__ __align__(16) float  d_Tco[128 * 32];   // cos(pi n (2j+1)/256)    [n][j]
__device__ __align__(16) float  d_Tse[128 * 32];   // -sin(2pi n j/256)       [n][j]
__device__ __align__(16) float  d_Tso[128 * 32];   // -sin(pi n (2j+1)/256)   [n][j]
__device__ __align__(16) float  d_Ipe[32 * 128];   // c2j cos(2pi n j/256)    [j][n]
__device__ __align__(16) float  d_Ipo[32 * 128];   // 2 cos(pi n (2j+1)/256)  [j][n]
__device__ __align__(16) float  d_Iqe[32 * 128];   // c2j sin(2pi n j/256)    [j][n]
__device__ __align__(16) float  d_Iqo[32 * 128];   // 2 sin(pi n (2j+1)/256)  [j][n]
__device__ __align__(16) float2 d_E[W_];           // e^{+2 pi i t/512}
__device__ __align__(16) float  d_xp[(size_t)NROW * KF];
__device__ __align__(16) float2 d_G[B_ * H_ * KF];           // (filt-1)/256
__device__ __align__(16) float  d_U[(size_t)NROW * 2 * KF];  // (b,c,h,k{r,i})
__device__ __align__(16) float  d_V[(size_t)NROW * 2 * KF];  // (b,c,n,k{r,i})

__device__ __forceinline__ float2 cadd(float2 a, float2 b){ return make_float2(a.x+b.x, a.y+b.y); }
__device__ __forceinline__ float2 csub(float2 a, float2 b){ return make_float2(a.x-b.x, a.y-b.y); }
__device__ __forceinline__ float2 cmul(float2 a, float2 b){
    return make_float2(fmaf(a.x,b.x,-a.y*b.y), fmaf(a.x,b.y,a.y*b.x));
}

// ---------------- in-register FFT16 (natural order), INV=0 fwd, 1 inv ----------
template<int INV>
__device__ __forceinline__ void fft16(float2* v) {
    const float C1 = 0.9238795325112867f, S1 = 0.3826834323650898f;
    const float C2 = 0.7071067811865476f;
    const float sg = INV ? 1.f : -1.f;
    const float2 w1 = make_float2( C1, sg*S1);
    const float2 w2 = make_float2( C2, sg*C2);
    const float2 w3 = make_float2( S1, sg*C1);
    const float2 w4 = make_float2(0.f, sg);
    const float2 w6 = make_float2(-C2, sg*C2);
    const float2 w9 = make_float2(-C1, -sg*S1);
    float2 A[16];
#pragma unroll
    for (int n0 = 0; n0 < 4; n0++) {
        float2 a=v[n0], b=v[n0+4], c=v[n0+8], d=v[n0+12];
        float2 t0=cadd(a,c), t1=csub(a,c), t2=cadd(b,d), t3=csub(b,d);
        float2 jt3 = INV ? make_float2(-t3.y, t3.x) : make_float2(t3.y, -t3.x);
        A[n0*4+0]=cadd(t0,t2); A[n0*4+1]=cadd(t1,jt3);
        A[n0*4+2]=csub(t0,t2); A[n0*4+3]=csub(t1,jt3);
    }
    A[5]=cmul(A[5],w1);  A[6]=cmul(A[6],w2);  A[7]=cmul(A[7],w3);
    A[9]=cmul(A[9],w2);  A[10]=cmul(A[10],w4); A[11]=cmul(A[11],w6);
    A[13]=cmul(A[13],w3); A[14]=cmul(A[14],w6); A[15]=cmul(A[15],w9);
#pragma unroll
    for (int k1 = 0; k1 < 4; k1++) {
        float2 a=A[k1], b=A[4+k1], c=A[8+k1], d=A[12+k1];
        float2 t0=cadd(a,c), t1=csub(a,c), t2=cadd(b,d), t3=csub(b,d);
        float2 jt3 = INV ? make_float2(-t3.y, t3.x) : make_float2(t3.y, -t3.x);
        v[k1+0]=cadd(t0,t2); v[k1+4]=cadd(t1,jt3);
        v[k1+8]=csub(t0,t2); v[k1+12]=csub(t1,jt3);
    }
}

// ---------------- tables ----------------
__global__ void k_tables() {
    int t = blockIdx.x * 256 + threadIdx.x;     // 32768
    if (t < 512) {
        double s, c; sincospi((double)t / 256.0, &s, &c);
        d_E[t] = make_float2((float)c, (float)s);
    }
    int id = t >> 12, idx = t & 4095;
    double s, c;
    if (id < 4) {                               // fwd: idx = n*32 + j
        int n = idx >> 5, j = idx & 31;
        if (id == 0 || id == 2) sincospi((double)(n * j) / 128.0, &s, &c);
        else                    sincospi((double)(n * (2 * j + 1)) / 256.0, &s, &c);
        if (id == 0) d_Tce[idx] = (float)c;
        else if (id == 1) d_Tco[idx] = (float)c;
        else if (id == 2) d_Tse[idx] = (float)(-s);
        else              d_Tso[idx] = (float)(-s);
    } else {                                    // inv: idx = j*128 + n
        int j = idx >> 7, n = idx & 127;
        if (id == 4 || id == 6) sincospi((double)(n * j) / 128.0, &s, &c);
        else                    sincospi((double)(n * (2 * j + 1)) / 256.0, &s, &c);
        float ce = (j == 0) ? 1.f : 2.f;
        if (id == 4) d_Ipe[idx] = ce * (float)c;
        else if (id == 5) d_Ipo[idx] = 2.f * (float)c;
        else if (id == 6) d_Iqe[idx] = ce * (float)s;
        else              d_Iqo[idx] = 2.f * (float)s;
    }
}

// ---------------- pooling ----------------
__global__ void k_pool(const float* __restrict__ x) {
    int id = blockIdx.x * 256 + threadIdx.x;
    int j = id & 63;
    size_t row = (size_t)(id >> 6);
    const float* p = x + row * W_ + j * 8;
    float4 a = *(const float4*)p, b = *(const float4*)(p + 4);
    d_xp[id] = (a.x + a.y + a.z + a.w + b.x + b.y + b.z + b.w) * 0.125f;
}

// ---------------- K1 double-folded forward: K=128, 4 planes, vector loads -------
__global__ void __launch_bounds__(256) k_fwd(const float* __restrict__ x) {
    __shared__ float SEp[16][68], SEm[16][68], SOm[16][68], SOp[16][68];
    __shared__ float SCe[16][32], SCo[16][32], SSe[16][32], SSo[16][32];
    const int tid = threadIdx.x;
    const int tx = tid & 15, ty = tid >> 4;
    const long row0 = (long)blockIdx.x * 64;

    float re_e[4][2], re_o[4][2], im_e[4][2], im_o[4][2];
#pragma unroll
    for (int u = 0; u < 4; u++)
#pragma unroll
        for (int p = 0; p < 2; p++) {
            re_e[u][p] = 0.f; re_o[u][p] = 0.f;
            im_e[u][p] = 0.f; im_o[u][p] = 0.f;
        }

    for (int kc = 0; kc < 128; kc += 16) {
        __syncthreads();
        {   // A planes via aligned float4 loads + 2 fencepost scalars
            int r = tid >> 2, qg = tid & 3;
            const float* xp = x + (row0 + r) * W_;
            int o = kc + qg * 4;
            float4 av = *(const float4*)(xp + o);             // a[q] = x[n]
            float4 cv = *(const float4*)(xp + 256 + o);       // c[q] = x[256+n]
            float4 bv = *(const float4*)(xp + 252 - o);       // desc: b[1..3]
            float4 dv = *(const float4*)(xp + 508 - o);       // desc: d[1..3]
            float  bs = xp[256 - o];                          // b[0]
            float  ds = xp[(512 - o) & 511];                  // d[0]
            float aq[4] = {av.x, av.y, av.z, av.w};
            float cq[4] = {cv.x, cv.y, cv.z, cv.w};
            float bq[4] = {bs, bv.w, bv.z, bv.y};
            float dq[4] = {ds, dv.w, dv.z, dv.y};
#pragma unroll
            for (int q = 0; q < 4; q++) {
                float sa = aq[q] + dq[q], da = aq[q] - dq[q];
                float sb = bq[q] + cq[q], db = bq[q] - cq[q];
                float ep = sa + sb, em = sa - sb, om = da - db, op = da + db;
                int j = qg * 4 + q;
                if (kc + j == 0) { ep = 0.f; em = 0.f; om = 0.f; op = 0.f; }
                SEp[j][r] = ep; SEm[j][r] = em;
                SOm[j][r] = om; SOp[j][r] = op;
            }
        }
#pragma unroll
        for (int i = 0; i < 2; i++) {           // B tiles
            int f = tid + i * 256;
            int which = f >> 7, g = f & 127;
            int nl = g >> 3, c4 = (g & 7) * 4;
            const float* src =
                (which == 0 ? d_Tce : which == 1 ? d_Tco : which == 2 ? d_Tse : d_Tso)
                + (kc + nl) * 32 + c4;
            float4 v = *(const float4*)src;
            float* dst = (which == 0 ? &SCe[nl][c4] : which == 1 ? &SCo[nl][c4]
                        : which == 2 ? &SSe[nl][c4] : &SSo[nl][c4]);
            *(float4*)dst = v;
        }
        __syncthreads();
#pragma unroll
        for (int nl = 0; nl < 16; nl++) {
            float4 ep4 = *(const float4*)&SEp[nl][ty * 4];
            float4 em4 = *(const float4*)&SEm[nl][ty * 4];
            float4 om4 = *(const float4*)&SOm[nl][ty * 4];
            float4 op4 = *(const float4*)&SOp[nl][ty * 4];
            float2 ce = *(const float2*)&SCe[nl][tx * 2];
            float2 co = *(const float2*)&SCo[nl][tx * 2];
            float2 se = *(const float2*)&SSe[nl][tx * 2];
            float2 so = *(const float2*)&SSo[nl][tx * 2];
            float ep[4] = {ep4.x, ep4.y, ep4.z, ep4.w};
            float em[4] = {em4.x, em4.y, em4.z, em4.w};
            float om[4] = {om4.x, om4.y, om4.z, om4.w};
            float op[4] = {op4.x, op4.y, op4.z, op4.w};
            float cev[2] = {ce.x, ce.y}, cov[2] = {co.x, co.y};
            float sev[2] = {se.x, se.y}, sov[2] = {so.x, so.y};
#pragma unroll
            for (int u = 0; u < 4; u++)
#pragma unroll
                for (int p = 0; p < 2; p++) {
                    re_e[u][p] = fmaf(ep[u], cev[p], re_e[u][p]);
                    re_o[u][p] = fmaf(em[u], cov[p], re_o[u][p]);
                    im_e[u][p] = fmaf(om[u], sev[p], im_e[u][p]);
                    im_o[u][p] = fmaf(op[u], sov[p], im_o[u][p]);
                }
        }
    }
    // epilogue: boundary terms x[0], x[128], x[256], x[384]
#pragma unroll
    for (int u = 0; u < 4; u++) {
        long row = row0 + ty * 4 + u;
        const float* xp = x + row * W_;
        float x0 = xp[0], x128 = xp[128], x256 = xp[256], x384 = xp[384];
        float e128 = x128 + x384, o128 = x128 - x384;
        float* Up = d_U + row * 128 + tx * 8;
        float4 a, b;
        a.x = re_e[u][0] + x0 + e128 + x256;
        a.y = im_e[u][0];
        a.z = re_o[u][0] + x0 - x256;
        a.w = im_o[u][0] - o128;
        b.x = re_e[u][1] + x0 - e128 + x256;
        b.y = im_e[u][1];
        b.z = re_o[u][1] + x0 - x256;
        b.w = im_o[u][1] + o128;
        *(float4*)Up = a;
        *(float4*)(Up + 4) = b;
    }
}

// ---------------- filter (fast-math transcendentals) ----------------
__global__ void __launch_bounds__(256) k_filter(
    const float* __restrict__ w, const float* __restrict__ bias,
    const float* __restrict__ dt)
{
    __shared__ float ws[4096];
    __shared__ float bs[64];
    int tid = threadIdx.x;
#pragma unroll
    for (int i = tid; i < 4096; i += 256) ws[i] = w[i];
    if (tid < 64) bs[tid] = bias[tid];
    __syncthreads();

    int id = blockIdx.x * 256 + tid;
    int j = id & 63, h = (id >> 6) & 255, bb = id >> 14;
    float xv[64];
#pragma unroll
    for (int c = 0; c < 64; c++)
        xv[c] = d_xp[(((size_t)(bb * 64 + c)) * 256 + h) * 64 + j];
    float dtb = dt[bb];
    float pdt = 3.14159265358979323846f * dtb;
    float fr = 0.f, fi = 0.f;
    for (int r = 0; r < 32; r++) {
        float p1 = bs[r], p2 = bs[32 + r];
#pragma unroll
        for (int c = 0; c < 64; c++) {
            p1 = fmaf(ws[r * 64 + c], xv[c], p1);
            p2 = fmaf(ws[(32 + r) * 64 + c], xv[c], p2);
        }
        float nu  = __logf(1.f + __expf(p1));           // softplus
        float e2  = __expf(2.f * p2);
        float ang = pdt - __fdividef(2.f * pdt, e2 + 1.f);  // pdt * tanh(p2)
        float dec = __expf(-nu * dtb);
        float s, co; __sincosf(ang, &s, &co);
        fr = fmaf(dec, co, fr);
        fi = fmaf(dec, s, fi);
    }
    d_G[id] = make_float2((fr - 1.f) * 0.00390625f, fi * 0.00390625f);
}

// ---------------- fused H transform: V = IFFT_256( G .* FFT_256(U) ) ------------
#define PSTR 9
__global__ void __launch_bounds__(128) k_hfft() {
    __shared__ float SAr[256*PSTR], SAi[256*PSTR];
    __shared__ float SBr[256*PSTR], SBi[256*PSTR];
    __shared__ float2 Ws[256];
    const int bc = blockIdx.x;
    const int b = bc >> 6;
    const int t = threadIdx.x;
    const int kk = t & 7, u = t >> 3;

    for (int i = t; i < 256; i += 128) {
        float2 e = d_E[2 * i];
        Ws[i] = make_float2(e.x, -e.y);
    }
    const float2* Ub = (const float2*)d_U + (size_t)bc * 256 * 64;
    float2*       Vb = (float2*)d_V + (size_t)bc * 256 * 64;

    for (int kb = 0; kb < 64; kb += 8) {
        __syncthreads();
        for (int i = t; i < 2048; i += 128) {
            int h = i >> 3, k2 = i & 7;
            float2 uv = Ub[h * 64 + kb + k2];
            SAr[h * PSTR + k2] = uv.x; SAi[h * PSTR + k2] = uv.y;
        }
        __syncthreads();
        float2 v[16];
#pragma unroll
        for (int n2 = 0; n2 < 16; n2++) {
            int p = (u + 16 * n2) * PSTR + kk;
            v[n2] = make_float2(SAr[p], SAi[p]);
        }
        fft16<0>(v);
#pragma unroll
        for (int k2 = 1; k2 < 16; k2++) v[k2] = cmul(v[k2], Ws[u * k2]);
#pragma unroll
        for (int k2 = 0; k2 < 16; k2++) {
            int p = (k2 * 16 + u) * PSTR + kk;
            SBr[p] = v[k2].x; SBi[p] = v[k2].y;
        }
        __syncthreads();
#pragma unroll
        for (int n1 = 0; n1 < 16; n1++) {
            int p = (u * 16 + n1) * PSTR + kk;
            v[n1] = make_float2(SBr[p], SBi[p]);
        }
        fft16<0>(v);
#pragma unroll
        for (int r = 0; r < 16; r++) {
            float2 g = d_G[((size_t)b * 256 + u + 16 * r) * 64 + kb + kk];
            v[r] = cmul(v[r], g);
        }
        fft16<1>(v);
#pragma unroll
        for (int n2 = 0; n2 < 16; n2++) {
            float2 wc = Ws[u * n2]; wc.y = -wc.y;
            float2 r = cmul(v[n2], wc);
            int p = (n2 * 16 + u) * PSTR + kk;
            SAr[p] = r.x; SAi[p] = r.y;
        }
        __syncthreads();
#pragma unroll
        for (int m1 = 0; m1 < 16; m1++) {
            int p = (u * 16 + m1) * PSTR + kk;
            v[m1] = make_float2(SAr[p], SAi[p]);
        }
        fft16<1>(v);
#pragma unroll
        for (int n1 = 0; n1 < 16; n1++)
            Vb[(u + 16 * n1) * 64 + kb + kk] = v[n1];
    }
}

// ---------------- K5 double-folded inverse: 4 accums -> 4 output columns --------
__global__ void __launch_bounds__(256) k_inv(const float* __restrict__ x,
                                             float* __restrict__ out) {
    __shared__ float4 AV[16][65];
    __shared__ float SPe[16][64], SPo[16][64], SQe[16][64], SQo[16][64];
    const int tid = threadIdx.x;
    const int tx = tid & 15, ty = tid >> 4;
    const long row0 = (long)blockIdx.x * 64;
    const int n0 = blockIdx.y * 64;

    float Pe[4][4], Po[4][4], Qe[4][4], Qo[4][4];
#pragma unroll
    for (int u = 0; u < 4; u++)
#pragma unroll
        for (int w = 0; w < 4; w++) { Pe[u][w]=0.f; Po[u][w]=0.f; Qe[u][w]=0.f; Qo[u][w]=0.f; }

    for (int jc = 0; jc < 32; jc += 16) {
        __syncthreads();
#pragma unroll
        for (int i = 0; i < 4; i++) {
            int f = tid + i * 256;
            int r = f >> 4, jl = f & 15;
            AV[jl][r] = *(const float4*)&d_V[(row0 + r) * 128 + (jc + jl) * 4];
        }
#pragma unroll
        for (int i = 0; i < 4; i++) {
            int f = tid + i * 256;
            int which = f >> 8, g = f & 255;
            int jl = g >> 4, n4 = (g & 15) * 4;
            const float* src =
                (which == 0 ? d_Ipe : which == 1 ? d_Ipo : which == 2 ? d_Iqe : d_Iqo)
                + (jc + jl) * 128 + n0 + n4;
            float* dst = (which == 0 ? &SPe[jl][n4] : which == 1 ? &SPo[jl][n4]
                        : which == 2 ? &SQe[jl][n4] : &SQo[jl][n4]);
            *(float4*)dst = *(const float4*)src;
        }
        __syncthreads();
#pragma unroll
        for (int jl = 0; jl < 16; jl++) {
            float4 av[4];
#pragma unroll
            for (int u = 0; u < 4; u++) av[u] = AV[jl][ty * 4 + u];
            float4 pe4 = *(const float4*)&SPe[jl][tx * 4];
            float4 po4 = *(const float4*)&SPo[jl][tx * 4];
            float4 qe4 = *(const float4*)&SQe[jl][tx * 4];
            float4 qo4 = *(const float4*)&SQo[jl][tx * 4];
            float pe[4] = {pe4.x, pe4.y, pe4.z, pe4.w};
            float po[4] = {po4.x, po4.y, po4.z, po4.w};
            float qe[4] = {qe4.x, qe4.y, qe4.z, qe4.w};
            float qo[4] = {qo4.x, qo4.y, qo4.z, qo4.w};
#pragma unroll
            for (int u = 0; u < 4; u++)
#pragma unroll
                for (int w = 0; w < 4; w++) {
                    Pe[u][w] = fmaf(av[u].x, pe[w], Pe[u][w]);
                    Qe[u][w] = fmaf(av[u].y, qe[w], Qe[u][w]);
                    Po[u][w] = fmaf(av[u].z, po[w], Po[u][w]);
                    Qo[u][w] = fmaf(av[u].w, qo[w], Qo[u][w]);
                }
        }
    }
    const float s = 1.f / 512.f;
#pragma unroll
    for (int u = 0; u < 4; u++) {
        long row = row0 + ty * 4 + u;
        const float* xr = x + row * W_;
        float* orow = out + row * W_;
        int nn0 = n0 + tx * 4;
        float4 xf = *(const float4*)(xr + nn0);
        float4 xg = *(const float4*)(xr + 256 + nn0);
        float4 o1, o2;
        float d1[4], d2[4], d3[4], d4[4];
#pragma unroll
        for (int w = 0; w < 4; w++) {
            float pp = Pe[u][w] + Po[u][w], pm = Pe[u][w] - Po[u][w];
            float qp = Qe[u][w] + Qo[u][w], qm = Qe[u][w] - Qo[u][w];
            d1[w] = pp - qp;
            d2[w] = pp + qp;
            d3[w] = pm + qm;
            d4[w] = pm - qm;
        }
        o1.x = fmaf(d1[0], s, xf.x); o1.y = fmaf(d1[1], s, xf.y);
        o1.z = fmaf(d1[2], s, xf.z); o1.w = fmaf(d1[3], s, xf.w);
        o2.x = fmaf(d4[0], s, xg.x); o2.y = fmaf(d4[1], s, xg.y);
        o2.z = fmaf(d4[2], s, xg.z); o2.w = fmaf(d4[3], s, xg.w);
        *(float4*)(orow + nn0) = o1;
        *(float4*)(orow + 256 + nn0) = o2;
#pragma unroll
        for (int w = 0; w < 4; w++) {
            int i2 = (512 - (nn0 + w)) & 511;
            orow[i2] = fmaf(d2[w], s, xr[i2]);
            int i3 = 256 - (nn0 + w);
            orow[i3] = fmaf(d3[w], s, xr[i3]);
        }
    }
}

// ---------------- edge columns 128 & 384 ----------------
__global__ void k_edge(const float* __restrict__ x, float* __restrict__ out) {
    int tid = threadIdx.x;
    int lane = tid & 31, wr = tid >> 5;
    long row = (long)blockIdx.x * 8 + wr;
    float4 v = *(const float4*)&d_V[row * 128 + lane * 4];
    float sg = (lane & 1) ? -1.f : 1.f;
    float pe = ((lane == 0) ? 1.f : 2.f) * sg * v.x;
    float qo = 2.f * sg * v.w;
#pragma unroll
    for (int o = 16; o > 0; o >>= 1) {
        pe += __shfl_down_sync(0xffffffffu, pe, o);
        qo += __shfl_down_sync(0xffffffffu, qo, o);
    }
    if (lane == 0) {
        const float s = 1.f / 512.f;
        out[row * W_ + 128] = fmaf(pe - qo, s, x[row * W_ + 128]);
        out[row * W_ + 384] = fmaf(pe + qo, s, x[row * W_ + 384]);
    }
}

// ---------------- launch ----------------
extern "C" void kernel_launch(void* const* d_in, const int* in_sizes, int n_in,
                              void* d_out, int out_size) {
    const float* x    = (const float*)d_in[0];
    const float* dt   = (const float*)d_in[1];
    const float* w    = (const float*)d_in[2];
    const float* bias = (const float*)d_in[3];
    float* out = (float*)d_out;

    k_tables<<<128, 256>>>();
    k_pool<<<NROW * 64 / 256, 256>>>(x);
    k_fwd<<<NROW / 64, 256>>>(x);
    k_filter<<<B_ * H_ * KF / 256, 256>>>(w, bias, dt);
    k_hfft<<<B_ * C_, 128>>>();
    k_inv<<<dim3(NROW / 64, 2), 256>>>(x, out);
    k_edge<<<NROW / 8, 256>>>(x, out);
}

// round 11
// speedup vs baseline: 2.8485x; 1.0480x over previous
#include <cuda_runtime.h>
#include <math.h>

#define B_ 8
#define C_ 64
#define H_ 256
#define W_ 512
#define KF 64
#define NROW (B_*C_*H_)  // 131072 rows

// ---------------- static device scratch (allocation-free rule) ----------------
__device__ __align__(16) float  d_Tce[128 * 32];   // cos(2pi n j/256)        [n][j]
__device__ __align__(16) float  d_Tco[128 * 32];   // cos(pi n (2j+1)/256)    [n][j]
__device__ __align__(16) float  d_Tse[128 * 32];   // -sin(2pi n j/256)       [n][j]
__device__ __align__(16) float  d_Tso[128 * 32];   // -sin(pi n (2j+1)/256)   [n][j]
__device__ __align__(16) float  d_Ipe[32 * 128];   // c2j cos(2pi n j/256)    [j][n]
__device__ __align__(16) float  d_Ipo[32 * 128];   // 2 cos(pi n (2j+1)/256)  [j][n]
__device__ __align__(16) float  d_Iqe[32 * 128];   // c2j sin(2pi n j/256)    [j][n]
__device__ __align__(16) float  d_Iqo[32 * 128];   // 2 sin(pi n (2j+1)/256)  [j][n]
__device__ __align__(16) float2 d_E[W_];           // e^{+2 pi i t/512}
__device__ __align__(16) float  d_xp[(size_t)NROW * KF];
__device__ __align__(16) float2 d_G[B_ * H_ * KF];           // (filt-1)/256
__device__ __align__(16) float  d_U[(size_t)NROW * 2 * KF];  // (b,c,h,k{r,i})
__device__ __align__(16) float  d_V[(size_t)NROW * 2 * KF];  // (b,c,n,k{r,i})

__device__ __forceinline__ float2 cadd(float2 a, float2 b){ return make_float2(a.x+b.x, a.y+b.y); }
__device__ __forceinline__ float2 csub(float2 a, float2 b){ return make_float2(a.x-b.x, a.y-b.y); }
__device__ __forceinline__ float2 cmul(float2 a, float2 b){
    return make_float2(fmaf(a.x,b.x,-a.y*b.y), fmaf(a.x,b.y,a.y*b.x));
}

// ---------------- in-register FFT16 (natural order), INV=0 fwd, 1 inv ----------
template<int INV>
__device__ __forceinline__ void fft16(float2* v) {
    const float C1 = 0.9238795325112867f, S1 = 0.3826834323650898f;
    const float C2 = 0.7071067811865476f;
    const float sg = INV ? 1.f : -1.f;
    const float2 w1 = make_float2( C1, sg*S1);
    const float2 w2 = make_float2( C2, sg*C2);
    const float2 w3 = make_float2( S1, sg*C1);
    const float2 w4 = make_float2(0.f, sg);
    const float2 w6 = make_float2(-C2, sg*C2);
    const float2 w9 = make_float2(-C1, -sg*S1);
    float2 A[16];
#pragma unroll
    for (int n0 = 0; n0 < 4; n0++) {
        float2 a=v[n0], b=v[n0+4], c=v[n0+8], d=v[n0+12];
        float2 t0=cadd(a,c), t1=csub(a,c), t2=cadd(b,d), t3=csub(b,d);
        float2 jt3 = INV ? make_float2(-t3.y, t3.x) : make_float2(t3.y, -t3.x);
        A[n0*4+0]=cadd(t0,t2); A[n0*4+1]=cadd(t1,jt3);
        A[n0*4+2]=csub(t0,t2); A[n0*4+3]=csub(t1,jt3);
    }
    A[5]=cmul(A[5],w1);  A[6]=cmul(A[6],w2);  A[7]=cmul(A[7],w3);
    A[9]=cmul(A[9],w2);  A[10]=cmul(A[10],w4); A[11]=cmul(A[11],w6);
    A[13]=cmul(A[13],w3); A[14]=cmul(A[14],w6); A[15]=cmul(A[15],w9);
#pragma unroll
    for (int k1 = 0; k1 < 4; k1++) {
        float2 a=A[k1], b=A[4+k1], c=A[8+k1], d=A[12+k1];
        float2 t0=cadd(a,c), t1=csub(a,c), t2=cadd(b,d), t3=csub(b,d);
        float2 jt3 = INV ? make_float2(-t3.y, t3.x) : make_float2(t3.y, -t3.x);
        v[k1+0]=cadd(t0,t2); v[k1+4]=cadd(t1,jt3);
        v[k1+8]=csub(t0,t2); v[k1+12]=csub(t1,jt3);
    }
}

// ---------------- tables ----------------
__global__ void k_tables() {
    int t = blockIdx.x * 256 + threadIdx.x;     // 32768
    if (t < 512) {
        double s, c; sincospi((double)t / 256.0, &s, &c);
        d_E[t] = make_float2((float)c, (float)s);
    }
    int id = t >> 12, idx = t & 4095;
    double s, c;
    if (id < 4) {                               // fwd: idx = n*32 + j
        int n = idx >> 5, j = idx & 31;
        if (id == 0 || id == 2) sincospi((double)(n * j) / 128.0, &s, &c);
        else                    sincospi((double)(n * (2 * j + 1)) / 256.0, &s, &c);
        if (id == 0) d_Tce[idx] = (float)c;
        else if (id == 1) d_Tco[idx] = (float)c;
        else if (id == 2) d_Tse[idx] = (float)(-s);
        else              d_Tso[idx] = (float)(-s);
    } else {                                    // inv: idx = j*128 + n
        int j = idx >> 7, n = idx & 127;
        if (id == 4 || id == 6) sincospi((double)(n * j) / 128.0, &s, &c);
        else                    sincospi((double)(n * (2 * j + 1)) / 256.0, &s, &c);
        float ce = (j == 0) ? 1.f : 2.f;
        if (id == 4) d_Ipe[idx] = ce * (float)c;
        else if (id == 5) d_Ipo[idx] = 2.f * (float)c;
        else if (id == 6) d_Iqe[idx] = ce * (float)s;
        else              d_Iqo[idx] = 2.f * (float)s;
    }
}

// ---------------- K1 double-folded forward + fused pooling ----------------
__global__ void __launch_bounds__(256) k_fwd(const float* __restrict__ x) {
    __shared__ float SEp[16][68], SEm[16][68], SOm[16][68], SOp[16][68];
    __shared__ float SCe[16][32], SCo[16][32], SSe[16][32], SSo[16][32];
    const int tid = threadIdx.x;
    const int tx = tid & 15, ty = tid >> 4;
    const long row0 = (long)blockIdx.x * 64;

    float re_e[4][2], re_o[4][2], im_e[4][2], im_o[4][2];
#pragma unroll
    for (int u = 0; u < 4; u++)
#pragma unroll
        for (int p = 0; p < 2; p++) {
            re_e[u][p] = 0.f; re_o[u][p] = 0.f;
            im_e[u][p] = 0.f; im_o[u][p] = 0.f;
        }

    for (int kc = 0; kc < 128; kc += 16) {
        __syncthreads();
        {   // A planes + fused pooling (the 4 float4 streams tile x exactly once)
            int r = tid >> 2, qg = tid & 3;
            const float* xp = x + (row0 + r) * W_;
            int o = kc + qg * 4;
            float4 av = *(const float4*)(xp + o);
            float4 cv = *(const float4*)(xp + 256 + o);
            float4 bv = *(const float4*)(xp + 252 - o);
            float4 dv = *(const float4*)(xp + 508 - o);
            float  bs = xp[256 - o];
            float  ds = xp[(512 - o) & 511];
            // pooling partial sums (pair of threads qg^1 completes each 8-bin)
            float sA = (av.x + av.y) + (av.z + av.w);
            float sB = (bv.x + bv.y) + (bv.z + bv.w);
            float sC = (cv.x + cv.y) + (cv.z + cv.w);
            float sD = (dv.x + dv.y) + (dv.z + dv.w);
            sA += __shfl_xor_sync(0xffffffffu, sA, 1);
            sB += __shfl_xor_sync(0xffffffffu, sB, 1);
            sC += __shfl_xor_sync(0xffffffffu, sC, 1);
            sD += __shfl_xor_sync(0xffffffffu, sD, 1);
            if ((qg & 1) == 0) {
                int g = (kc >> 3) + (qg >> 1);
                float* xpr = d_xp + (row0 + r) * 64;
                xpr[g]      = sA * 0.125f;
                xpr[31 - g] = sB * 0.125f;
                xpr[32 + g] = sC * 0.125f;
                xpr[63 - g] = sD * 0.125f;
            }
            float aq[4] = {av.x, av.y, av.z, av.w};
            float cq[4] = {cv.x, cv.y, cv.z, cv.w};
            float bq[4] = {bs, bv.w, bv.z, bv.y};
            float dq[4] = {ds, dv.w, dv.z, dv.y};
#pragma unroll
            for (int q = 0; q < 4; q++) {
                float sa = aq[q] + dq[q], da = aq[q] - dq[q];
                float sb = bq[q] + cq[q], db = bq[q] - cq[q];
                float ep = sa + sb, em = sa - sb, om = da - db, op = da + db;
                int j = qg * 4 + q;
                if (kc + j == 0) { ep = 0.f; em = 0.f; om = 0.f; op = 0.f; }
                SEp[j][r] = ep; SEm[j][r] = em;
                SOm[j][r] = om; SOp[j][r] = op;
            }
        }
#pragma unroll
        for (int i = 0; i < 2; i++) {           // B tiles
            int f = tid + i * 256;
            int which = f >> 7, g = f & 127;
            int nl = g >> 3, c4 = (g & 7) * 4;
            const float* src =
                (which == 0 ? d_Tce : which == 1 ? d_Tco : which == 2 ? d_Tse : d_Tso)
                + (kc + nl) * 32 + c4;
            float4 v = *(const float4*)src;
            float* dst = (which == 0 ? &SCe[nl][c4] : which == 1 ? &SCo[nl][c4]
                        : which == 2 ? &SSe[nl][c4] : &SSo[nl][c4]);
            *(float4*)dst = v;
        }
        __syncthreads();
#pragma unroll
        for (int nl = 0; nl < 16; nl++) {
            float4 ep4 = *(const float4*)&SEp[nl][ty * 4];
            float4 em4 = *(const float4*)&SEm[nl][ty * 4];
            float4 om4 = *(const float4*)&SOm[nl][ty * 4];
            float4 op4 = *(const float4*)&SOp[nl][ty * 4];
            float2 ce = *(const float2*)&SCe[nl][tx * 2];
            float2 co = *(const float2*)&SCo[nl][tx * 2];
            float2 se = *(const float2*)&SSe[nl][tx * 2];
            float2 so = *(const float2*)&SSo[nl][tx * 2];
            float ep[4] = {ep4.x, ep4.y, ep4.z, ep4.w};
            float em[4] = {em4.x, em4.y, em4.z, em4.w};
            float om[4] = {om4.x, om4.y, om4.z, om4.w};
            float op[4] = {op4.x, op4.y, op4.z, op4.w};
            float cev[2] = {ce.x, ce.y}, cov[2] = {co.x, co.y};
            float sev[2] = {se.x, se.y}, sov[2] = {so.x, so.y};
#pragma unroll
            for (int u = 0; u < 4; u++)
#pragma unroll
                for (int p = 0; p < 2; p++) {
                    re_e[u][p] = fmaf(ep[u], cev[p], re_e[u][p]);
                    re_o[u][p] = fmaf(em[u], cov[p], re_o[u][p]);
                    im_e[u][p] = fmaf(om[u], sev[p], im_e[u][p]);
                    im_o[u][p] = fmaf(op[u], sov[p], im_o[u][p]);
                }
        }
    }
    // epilogue: boundary terms x[0], x[128], x[256], x[384]
#pragma unroll
    for (int u = 0; u < 4; u++) {
        long row = row0 + ty * 4 + u;
        const float* xp = x + row * W_;
        float x0 = xp[0], x128 = xp[128], x256 = xp[256], x384 = xp[384];
        float e128 = x128 + x384, o128 = x128 - x384;
        float* Up = d_U + row * 128 + tx * 8;
        float4 a, b;
        a.x = re_e[u][0] + x0 + e128 + x256;
        a.y = im_e[u][0];
        a.z = re_o[u][0] + x0 - x256;
        a.w = im_o[u][0] - o128;
        b.x = re_e[u][1] + x0 - e128 + x256;
        b.y = im_e[u][1];
        b.z = re_o[u][1] + x0 - x256;
        b.w = im_o[u][1] + o128;
        *(float4*)Up = a;
        *(float4*)(Up + 4) = b;
    }
}

// ---------------- filter (fast-math, float4 LDS) ----------------
__global__ void __launch_bounds__(256) k_filter(
    const float* __restrict__ w, const float* __restrict__ bias,
    const float* __restrict__ dt)
{
    __shared__ float ws[4096];
    __shared__ float bs[64];
    int tid = threadIdx.x;
#pragma unroll
    for (int i = tid; i < 4096; i += 256) ws[i] = w[i];
    if (tid < 64) bs[tid] = bias[tid];
    __syncthreads();

    int id = blockIdx.x * 256 + tid;
    int j = id & 63, h = (id >> 6) & 255, bb = id >> 14;
    float xv[64];
#pragma unroll
    for (int c = 0; c < 64; c++)
        xv[c] = d_xp[(((size_t)(bb * 64 + c)) * 256 + h) * 64 + j];
    float dtb = dt[bb];
    float pdt = 3.14159265358979323846f * dtb;
    float fr = 0.f, fi = 0.f;
    for (int r = 0; r < 32; r++) {
        float p1 = bs[r], p2 = bs[32 + r];
#pragma unroll
        for (int c4 = 0; c4 < 16; c4++) {
            float4 w1 = *(const float4*)&ws[r * 64 + c4 * 4];
            float4 w2 = *(const float4*)&ws[(32 + r) * 64 + c4 * 4];
            p1 = fmaf(w1.x, xv[c4*4+0], p1); p2 = fmaf(w2.x, xv[c4*4+0], p2);
            p1 = fmaf(w1.y, xv[c4*4+1], p1); p2 = fmaf(w2.y, xv[c4*4+1], p2);
            p1 = fmaf(w1.z, xv[c4*4+2], p1); p2 = fmaf(w2.z, xv[c4*4+2], p2);
            p1 = fmaf(w1.w, xv[c4*4+3], p1); p2 = fmaf(w2.w, xv[c4*4+3], p2);
        }
        float nu  = __logf(1.f + __expf(p1));
        float e2  = __expf(2.f * p2);
        float ang = pdt - __fdividef(2.f * pdt, e2 + 1.f);
        float dec = __expf(-nu * dtb);
        float s, co; __sincosf(ang, &s, &co);
        fr = fmaf(dec, co, fr);
        fi = fmaf(dec, s, fi);
    }
    d_G[id] = make_float2((fr - 1.f) * 0.00390625f, fi * 0.00390625f);
}

// ---------------- fused H transform: V = IFFT_256( G .* FFT_256(U) ) ------------
// grid = B_*C_*2; adjacent blocks share a (b,c) and split the 64 k-bins.
#define PSTR 9
__global__ void __launch_bounds__(128) k_hfft() {
    __shared__ float SAr[256*PSTR], SAi[256*PSTR];
    __shared__ float SBr[256*PSTR], SBi[256*PSTR];
    __shared__ float2 Ws[256];
    const int bc = blockIdx.x >> 1;
    const int half = blockIdx.x & 1;
    const int b = bc >> 6;
    const int t = threadIdx.x;
    const int kk = t & 7, u = t >> 3;

    for (int i = t; i < 256; i += 128) {
        float2 e = d_E[2 * i];
        Ws[i] = make_float2(e.x, -e.y);
    }
    const float2* Ub = (const float2*)d_U + (size_t)bc * 256 * 64;
    float2*       Vb = (float2*)d_V + (size_t)bc * 256 * 64;

    for (int kb = half * 32; kb < half * 32 + 32; kb += 8) {
        __syncthreads();
        for (int i = t; i < 2048; i += 128) {
            int h = i >> 3, k2 = i & 7;
            float2 uv = Ub[h * 64 + kb + k2];
            SAr[h * PSTR + k2] = uv.x; SAi[h * PSTR + k2] = uv.y;
        }
        __syncthreads();
        float2 v[16];
#pragma unroll
        for (int n2 = 0; n2 < 16; n2++) {
            int p = (u + 16 * n2) * PSTR + kk;
            v[n2] = make_float2(SAr[p], SAi[p]);
        }
        fft16<0>(v);
#pragma unroll
        for (int k2 = 1; k2 < 16; k2++) v[k2] = cmul(v[k2], Ws[u * k2]);
#pragma unroll
        for (int k2 = 0; k2 < 16; k2++) {
            int p = (k2 * 16 + u) * PSTR + kk;
            SBr[p] = v[k2].x; SBi[p] = v[k2].y;
        }
        __syncthreads();
#pragma unroll
        for (int n1 = 0; n1 < 16; n1++) {
            int p = (u * 16 + n1) * PSTR + kk;
            v[n1] = make_float2(SBr[p], SBi[p]);
        }
        fft16<0>(v);
#pragma unroll
        for (int r = 0; r < 16; r++) {
            float2 g = d_G[((size_t)b * 256 + u + 16 * r) * 64 + kb + kk];
            v[r] = cmul(v[r], g);
        }
        fft16<1>(v);
#pragma unroll
        for (int n2 = 0; n2 < 16; n2++) {
            float2 wc = Ws[u * n2]; wc.y = -wc.y;
            float2 r = cmul(v[n2], wc);
            int p = (n2 * 16 + u) * PSTR + kk;
            SAr[p] = r.x; SAi[p] = r.y;
        }
        __syncthreads();
#pragma unroll
        for (int m1 = 0; m1 < 16; m1++) {
            int p = (u * 16 + m1) * PSTR + kk;
            v[m1] = make_float2(SAr[p], SAi[p]);
        }
        fft16<1>(v);
#pragma unroll
        for (int n1 = 0; n1 < 16; n1++)
            Vb[(u + 16 * n1) * 64 + kb + kk] = v[n1];
    }
}

// ---------------- K5 double-folded inverse ----------------
__global__ void __launch_bounds__(256) k_inv(const float* __restrict__ x,
                                             float* __restrict__ out) {
    __shared__ float4 AV[16][65];
    __shared__ float SPe[16][64], SPo[16][64], SQe[16][64], SQo[16][64];
    const int tid = threadIdx.x;
    const int tx = tid & 15, ty = tid >> 4;
    const long row0 = (long)blockIdx.x * 64;
    const int n0 = blockIdx.y * 64;

    float Pe[4][4], Po[4][4], Qe[4][4], Qo[4][4];
#pragma unroll
    for (int u = 0; u < 4; u++)
#pragma unroll
        for (int w = 0; w < 4; w++) { Pe[u][w]=0.f; Po[u][w]=0.f; Qe[u][w]=0.f; Qo[u][w]=0.f; }

    for (int jc = 0; jc < 32; jc += 16) {
        __syncthreads();
#pragma unroll
        for (int i = 0; i < 4; i++) {
            int f = tid + i * 256;
            int r = f >> 4, jl = f & 15;
            AV[jl][r] = *(const float4*)&d_V[(row0 + r) * 128 + (jc + jl) * 4];
        }
#pragma unroll
        for (int i = 0; i < 4; i++) {
            int f = tid + i * 256;
            int which = f >> 8, g = f & 255;
            int jl = g >> 4, n4 = (g & 15) * 4;
            const float* src =
                (which == 0 ? d_Ipe : which == 1 ? d_Ipo : which == 2 ? d_Iqe : d_Iqo)
                + (jc + jl) * 128 + n0 + n4;
            float* dst = (which == 0 ? &SPe[jl][n4] : which == 1 ? &SPo[jl][n4]
                        : which == 2 ? &SQe[jl][n4] : &SQo[jl][n4]);
            *(float4*)dst = *(const float4*)src;
        }
        __syncthreads();
#pragma unroll
        for (int jl = 0; jl < 16; jl++) {
            float4 av[4];
#pragma unroll
            for (int u = 0; u < 4; u++) av[u] = AV[jl][ty * 4 + u];
            float4 pe4 = *(const float4*)&SPe[jl][tx * 4];
            float4 po4 = *(const float4*)&SPo[jl][tx * 4];
            float4 qe4 = *(const float4*)&SQe[jl][tx * 4];
            float4 qo4 = *(const float4*)&SQo[jl][tx * 4];
            float pe[4] = {pe4.x, pe4.y, pe4.z, pe4.w};
            float po[4] = {po4.x, po4.y, po4.z, po4.w};
            float qe[4] = {qe4.x, qe4.y, qe4.z, qe4.w};
            float qo[4] = {qo4.x, qo4.y, qo4.z, qo4.w};
#pragma unroll
            for (int u = 0; u < 4; u++)
#pragma unroll
                for (int w = 0; w < 4; w++) {
                    Pe[u][w] = fmaf(av[u].x, pe[w], Pe[u][w]);
                    Qe[u][w] = fmaf(av[u].y, qe[w], Qe[u][w]);
                    Po[u][w] = fmaf(av[u].z, po[w], Po[u][w]);
                    Qo[u][w] = fmaf(av[u].w, qo[w], Qo[u][w]);
                }
        }
    }
    const float s = 1.f / 512.f;
#pragma unroll
    for (int u = 0; u < 4; u++) {
        long row = row0 + ty * 4 + u;
        const float* xr = x + row * W_;
        float* orow = out + row * W_;
        int nn0 = n0 + tx * 4;
        float4 xf = *(const float4*)(xr + nn0);
        float4 xg = *(const float4*)(xr + 256 + nn0);
        float4 o1, o2;
        float d1[4], d2[4], d3[4], d4[4];
#pragma unroll
        for (int w = 0; w < 4; w++) {
            float pp = Pe[u][w] + Po[u][w], pm = Pe[u][w] - Po[u][w];
            float qp = Qe[u][w] + Qo[u][w], qm = Qe[u][w] - Qo[u][w];
            d1[w] = pp - qp;    // y[n]
            d2[w] = pp + qp;    // y[512-n]
            d3[w] = pm + qm;    // y[256-n]
            d4[w] = pm - qm;    // y[256+n]
        }
        o1.x = fmaf(d1[0], s, xf.x); o1.y = fmaf(d1[1], s, xf.y);
        o1.z = fmaf(d1[2], s, xf.z); o1.w = fmaf(d1[3], s, xf.w);
        o2.x = fmaf(d4[0], s, xg.x); o2.y = fmaf(d4[1], s, xg.y);
        o2.z = fmaf(d4[2], s, xg.z); o2.w = fmaf(d4[3], s, xg.w);
        *(float4*)(orow + nn0) = o1;
        *(float4*)(orow + 256 + nn0) = o2;
        // mirror i3 = 256-nn0-w  (range [129,256], never wraps)
        {
            int b0 = 256 - nn0;
            orow[b0] = fmaf(d3[0], s, xr[b0]);
            float2 m = *(const float2*)(xr + b0 - 2);
            float2 r = make_float2(fmaf(d3[2], s, m.x), fmaf(d3[1], s, m.y));
            *(float2*)(orow + b0 - 2) = r;
            orow[b0 - 3] = fmaf(d3[3], s, xr[b0 - 3]);
        }
        // mirror i2 = (512-nn0-w)&511 (wrap only at nn0=0,w=0: same value as o1.x)
        {
            int b0 = (512 - nn0) & 511;
            orow[b0] = fmaf(d2[0], s, xr[b0]);
            int b2 = 510 - nn0;
            float2 m = *(const float2*)(xr + b2);
            float2 r = make_float2(fmaf(d2[2], s, m.x), fmaf(d2[1], s, m.y));
            *(float2*)(orow + b2) = r;
            orow[b2 - 1] = fmaf(d2[3], s, xr[b2 - 1]);
        }
    }
}

// ---------------- edge columns 128 & 384 ----------------
__global__ void k_edge(const float* __restrict__ x, float* __restrict__ out) {
    int tid = threadIdx.x;
    int lane = tid & 31, wr = tid >> 5;
    long row = (long)blockIdx.x * 8 + wr;
    float4 v = *(const float4*)&d_V[row * 128 + lane * 4];
    float sg = (lane & 1) ? -1.f : 1.f;
    float pe = ((lane == 0) ? 1.f : 2.f) * sg * v.x;
    float qo = 2.f * sg * v.w;
#pragma unroll
    for (int o = 16; o > 0; o >>= 1) {
        pe += __shfl_down_sync(0xffffffffu, pe, o);
        qo += __shfl_down_sync(0xffffffffu, qo, o);
    }
    if (lane == 0) {
        const float s = 1.f / 512.f;
        out[row * W_ + 128] = fmaf(pe - qo, s, x[row * W_ + 128]);
        out[row * W_ + 384] = fmaf(pe + qo, s, x[row * W_ + 384]);
    }
}

// ---------------- launch ----------------
extern "C" void kernel_launch(void* const* d_in, const int* in_sizes, int n_in,
                              void* d_out, int out_size) {
    const float* x    = (const float*)d_in[0];
    const float* dt   = (const float*)d_in[1];
    const float* w    = (const float*)d_in[2];
    const float* bias = (const float*)d_in[3];
    float* out = (float*)d_out;

    k_tables<<<128, 256>>>();
    k_fwd<<<NROW / 64, 256>>>(x);          // also writes d_xp (fused pooling)
    k_filter<<<B_ * H_ * KF / 256, 256>>>(w, bias, dt);
    k_hfft<<<B_ * C_ * 2, 128>>>();
    k_inv<<<dim3(NROW / 64, 2), 256>>>(x, out);
    k_edge<<<NROW / 8, 256>>>(x, out);
}

// round 12
// speedup vs baseline: 3.0409x; 1.0675x over previous
#include <cuda_runtime.h>
#include <math.h>

#define B_ 8
#define C_ 64
#define H_ 256
#define W_ 512
#define KF 64
#define NROW (B_*C_*H_)  // 131072 rows

// ---------------- static device scratch (allocation-free rule) ----------------
__device__ __align__(16) float  d_Tce[128 * 32];   // cos(2pi n j/256)        [n][j]
__device__ __align__(16) float  d_Tco[128 * 32];   // cos(pi n (2j+1)/256)    [n][j]
__device__ __align__(16) float  d_Tse[128 * 32];   // -sin(2pi n j/256)       [n][j]
__device__ __align__(16) float  d_Tso[128 * 32];   // -sin(pi n (2j+1)/256)   [n][j]
__device__ __align__(16) float  d_Ipe[32 * 128];   // c2j cos(2pi n j/256)    [j][n]
__device__ __align__(16) float  d_Ipo[32 * 128];   // 2 cos(pi n (2j+1)/256)  [j][n]
__device__ __align__(16) float  d_Iqe[32 * 128];   // c2j sin(2pi n j/256)    [j][n]
__device__ __align__(16) float  d_Iqo[32 * 128];   // 2 sin(pi n (2j+1)/256)  [j][n]
__device__ __align__(16) float2 d_E[W_];           // e^{+2 pi i t/512}
__device__ __align__(16) float  d_xp[(size_t)NROW * KF];
__device__ __align__(16) float2 d_G[B_ * H_ * KF];           // (filt-1)/256
__device__ __align__(16) float  d_U[(size_t)NROW * 2 * KF];  // (b,c,h,k{r,i})
__device__ __align__(16) float  d_V[(size_t)NROW * 2 * KF];  // (b,c,n,k{r,i})

__device__ __forceinline__ float2 cadd(float2 a, float2 b){ return make_float2(a.x+b.x, a.y+b.y); }
__device__ __forceinline__ float2 csub(float2 a, float2 b){ return make_float2(a.x-b.x, a.y-b.y); }
__device__ __forceinline__ float2 cmul(float2 a, float2 b){
    return make_float2(fmaf(a.x,b.x,-a.y*b.y), fmaf(a.x,b.y,a.y*b.x));
}

// ---------------- in-register FFT16 (natural order), INV=0 fwd, 1 inv ----------
template<int INV>
__device__ __forceinline__ void fft16(float2* v) {
    const float C1 = 0.9238795325112867f, S1 = 0.3826834323650898f;
    const float C2 = 0.7071067811865476f;
    const float sg = INV ? 1.f : -1.f;
    const float2 w1 = make_float2( C1, sg*S1);
    const float2 w2 = make_float2( C2, sg*C2);
    const float2 w3 = make_float2( S1, sg*C1);
    const float2 w4 = make_float2(0.f, sg);
    const float2 w6 = make_float2(-C2, sg*C2);
    const float2 w9 = make_float2(-C1, -sg*S1);
    float2 A[16];
#pragma unroll
    for (int n0 = 0; n0 < 4; n0++) {
        float2 a=v[n0], b=v[n0+4], c=v[n0+8], d=v[n0+12];
        float2 t0=cadd(a,c), t1=csub(a,c), t2=cadd(b,d), t3=csub(b,d);
        float2 jt3 = INV ? make_float2(-t3.y, t3.x) : make_float2(t3.y, -t3.x);
        A[n0*4+0]=cadd(t0,t2); A[n0*4+1]=cadd(t1,jt3);
        A[n0*4+2]=csub(t0,t2); A[n0*4+3]=csub(t1,jt3);
    }
    A[5]=cmul(A[5],w1);  A[6]=cmul(A[6],w2);  A[7]=cmul(A[7],w3);
    A[9]=cmul(A[9],w2);  A[10]=cmul(A[10],w4); A[11]=cmul(A[11],w6);
    A[13]=cmul(A[13],w3); A[14]=cmul(A[14],w6); A[15]=cmul(A[15],w9);
#pragma unroll
    for (int k1 = 0; k1 < 4; k1++) {
        float2 a=A[k1], b=A[4+k1], c=A[8+k1], d=A[12+k1];
        float2 t0=cadd(a,c), t1=csub(a,c), t2=cadd(b,d), t3=csub(b,d);
        float2 jt3 = INV ? make_float2(-t3.y, t3.x) : make_float2(t3.y, -t3.x);
        v[k1+0]=cadd(t0,t2); v[k1+4]=cadd(t1,jt3);
        v[k1+8]=csub(t0,t2); v[k1+12]=csub(t1,jt3);
    }
}

// ---------------- tables ----------------
__global__ void k_tables() {
    int t = blockIdx.x * 256 + threadIdx.x;     // 32768
    if (t < 512) {
        double s, c; sincospi((double)t / 256.0, &s, &c);
        d_E[t] = make_float2((float)c, (float)s);
    }
    int id = t >> 12, idx = t & 4095;
    double s, c;
    if (id < 4) {                               // fwd: idx = n*32 + j
        int n = idx >> 5, j = idx & 31;
        if (id == 0 || id == 2) sincospi((double)(n * j) / 128.0, &s, &c);
        else                    sincospi((double)(n * (2 * j + 1)) / 256.0, &s, &c);
        if (id == 0) d_Tce[idx] = (float)c;
        else if (id == 1) d_Tco[idx] = (float)c;
        else if (id == 2) d_Tse[idx] = (float)(-s);
        else              d_Tso[idx] = (float)(-s);
    } else {                                    // inv: idx = j*128 + n
        int j = idx >> 7, n = idx & 127;
        if (id == 4 || id == 6) sincospi((double)(n * j) / 128.0, &s, &c);
        else                    sincospi((double)(n * (2 * j + 1)) / 256.0, &s, &c);
        float ce = (j == 0) ? 1.f : 2.f;
        if (id == 4) d_Ipe[idx] = ce * (float)c;
        else if (id == 5) d_Ipo[idx] = 2.f * (float)c;
        else if (id == 6) d_Iqe[idx] = ce * (float)s;
        else              d_Iqo[idx] = 2.f * (float)s;
    }
}

// ---------------- K1 forward: plane-split groups, 128 rows/block ----------------
__global__ void __launch_bounds__(256) k_fwd(const float* __restrict__ x) {
    __shared__ float SEp[16][132], SEm[16][132], SOm[16][132], SOp[16][132];
    __shared__ float SCe[16][32], SCo[16][32], SSe[16][32], SSo[16][32];
    const int tid = threadIdx.x;
    const long row0 = (long)blockIdx.x * 128;
    const int grp = tid >> 7;           // 0: even k (re_e,im_e), 1: odd k
    const int idx = tid & 127;
    const int rg  = idx >> 3;           // 16 row groups x 8 rows
    const int cg  = idx & 7;            // 8 col groups x 4 j

    float aR[8][4], aI[8][4];
#pragma unroll
    for (int m = 0; m < 8; m++)
#pragma unroll
        for (int w = 0; w < 4; w++) { aR[m][w] = 0.f; aI[m][w] = 0.f; }

    const int r = tid >> 1;             // 0..127 row for A-phase
    const int half = tid & 1;
    const float* xp = x + (row0 + r) * W_;
    float* xpr = d_xp + (row0 + r) * 64;

    for (int kc = 0; kc < 128; kc += 16) {
        __syncthreads();
        {   // A-phase fold + fused pooling (8-aligned, no shuffles)
            int o = kc + half * 8;
            float4 a0 = *(const float4*)(xp + o);
            float4 a1 = *(const float4*)(xp + o + 4);
            float4 c0 = *(const float4*)(xp + 256 + o);
            float4 c1 = *(const float4*)(xp + 260 + o);
            float4 bl = *(const float4*)(xp + 248 - o);
            float4 bh = *(const float4*)(xp + 252 - o);
            float4 dl = *(const float4*)(xp + 504 - o);
            float4 dh = *(const float4*)(xp + 508 - o);
            float  bsc = xp[256 - o];
            float  dsc = xp[(512 - o) & 511];
            int g = o >> 3;
            xpr[g]      = ((a0.x+a0.y)+(a0.z+a0.w)+(a1.x+a1.y)+(a1.z+a1.w))*0.125f;
            xpr[31 - g] = ((bl.x+bl.y)+(bl.z+bl.w)+(bh.x+bh.y)+(bh.z+bh.w))*0.125f;
            xpr[32 + g] = ((c0.x+c0.y)+(c0.z+c0.w)+(c1.x+c1.y)+(c1.z+c1.w))*0.125f;
            xpr[63 - g] = ((dl.x+dl.y)+(dl.z+dl.w)+(dh.x+dh.y)+(dh.z+dh.w))*0.125f;
            float aq[8] = {a0.x,a0.y,a0.z,a0.w,a1.x,a1.y,a1.z,a1.w};
            float cq[8] = {c0.x,c0.y,c0.z,c0.w,c1.x,c1.y,c1.z,c1.w};
            float bq[8] = {bsc,bh.w,bh.z,bh.y,bh.x,bl.w,bl.z,bl.y};
            float dq[8] = {dsc,dh.w,dh.z,dh.y,dh.x,dl.w,dl.z,dl.y};
            int jb = half * 8;
#pragma unroll
            for (int q = 0; q < 8; q++) {
                float sa = aq[q] + dq[q], da = aq[q] - dq[q];
                float sb = bq[q] + cq[q], db = bq[q] - cq[q];
                float ep = sa + sb, em = sa - sb, om = da - db, op = da + db;
                if (o + q == 0) { ep = 0.f; em = 0.f; om = 0.f; op = 0.f; }
                SEp[jb + q][r] = ep; SEm[jb + q][r] = em;
                SOm[jb + q][r] = om; SOp[jb + q][r] = op;
            }
        }
#pragma unroll
        for (int i = 0; i < 2; i++) {   // B tiles: 512 float4
            int f = tid + i * 256;
            int which = f >> 7, gg = f & 127;
            int nl = gg >> 3, c4 = (gg & 7) * 4;
            const float* src =
                (which == 0 ? d_Tce : which == 1 ? d_Tco : which == 2 ? d_Tse : d_Tso)
                + (kc + nl) * 32 + c4;
            float* dst = (which == 0 ? &SCe[nl][c4] : which == 1 ? &SCo[nl][c4]
                        : which == 2 ? &SSe[nl][c4] : &SSo[nl][c4]);
            *(float4*)dst = *(const float4*)src;
        }
        __syncthreads();
        const float* Ap = grp ? &SEm[0][0] : &SEp[0][0];
        const float* Ai = grp ? &SOp[0][0] : &SOm[0][0];
        const float* Bc = grp ? &SCo[0][0] : &SCe[0][0];
        const float* Bs = grp ? &SSo[0][0] : &SSe[0][0];
#pragma unroll
        for (int nl = 0; nl < 16; nl++) {
            float4 e0 = *(const float4*)(Ap + nl * 132 + rg * 8);
            float4 e1 = *(const float4*)(Ap + nl * 132 + rg * 8 + 4);
            float4 q0 = *(const float4*)(Ai + nl * 132 + rg * 8);
            float4 q1 = *(const float4*)(Ai + nl * 132 + rg * 8 + 4);
            float4 bc = *(const float4*)(Bc + nl * 32 + cg * 4);
            float4 bs = *(const float4*)(Bs + nl * 32 + cg * 4);
            float ev[8] = {e0.x,e0.y,e0.z,e0.w,e1.x,e1.y,e1.z,e1.w};
            float ov[8] = {q0.x,q0.y,q0.z,q0.w,q1.x,q1.y,q1.z,q1.w};
            float bcv[4] = {bc.x,bc.y,bc.z,bc.w};
            float bsv[4] = {bs.x,bs.y,bs.z,bs.w};
#pragma unroll
            for (int m = 0; m < 8; m++)
#pragma unroll
                for (int w = 0; w < 4; w++) {
                    aR[m][w] = fmaf(ev[m], bcv[w], aR[m][w]);
                    aI[m][w] = fmaf(ov[m], bsv[w], aI[m][w]);
                }
        }
    }
    // epilogue: boundary terms; float2 (re,im) stores
#pragma unroll
    for (int m = 0; m < 8; m++) {
        long row = row0 + rg * 8 + m;
        const float* xr = x + row * W_;
        float x0 = xr[0], x128 = xr[128], x256 = xr[256], x384 = xr[384];
        float e128 = x128 + x384, o128 = x128 - x384;
        float* Up = d_U + row * 128 + (grp ? 2 : 0);
#pragma unroll
        for (int w = 0; w < 4; w++) {
            int j = cg * 4 + w;
            float re, im;
            if (!grp) {
                re = aR[m][w] + x0 + x256 + ((j & 1) ? -e128 : e128);
                im = aI[m][w];
            } else {
                re = aR[m][w] + x0 - x256;
                im = aI[m][w] + ((j & 1) ? o128 : -o128);
            }
            *(float2*)(Up + 4 * j) = make_float2(re, im);
        }
    }
}

// ---------------- filter (fast-math, float4 LDS) ----------------
__global__ void __launch_bounds__(256) k_filter(
    const float* __restrict__ w, const float* __restrict__ bias,
    const float* __restrict__ dt)
{
    __shared__ float ws[4096];
    __shared__ float bs[64];
    int tid = threadIdx.x;
#pragma unroll
    for (int i = tid; i < 4096; i += 256) ws[i] = w[i];
    if (tid < 64) bs[tid] = bias[tid];
    __syncthreads();

    int id = blockIdx.x * 256 + tid;
    int j = id & 63, h = (id >> 6) & 255, bb = id >> 14;
    float xv[64];
#pragma unroll
    for (int c = 0; c < 64; c++)
        xv[c] = d_xp[(((size_t)(bb * 64 + c)) * 256 + h) * 64 + j];
    float dtb = dt[bb];
    float pdt = 3.14159265358979323846f * dtb;
    float fr = 0.f, fi = 0.f;
    for (int r = 0; r < 32; r++) {
        float p1 = bs[r], p2 = bs[32 + r];
#pragma unroll
        for (int c4 = 0; c4 < 16; c4++) {
            float4 w1 = *(const float4*)&ws[r * 64 + c4 * 4];
            float4 w2 = *(const float4*)&ws[(32 + r) * 64 + c4 * 4];
            p1 = fmaf(w1.x, xv[c4*4+0], p1); p2 = fmaf(w2.x, xv[c4*4+0], p2);
            p1 = fmaf(w1.y, xv[c4*4+1], p1); p2 = fmaf(w2.y, xv[c4*4+1], p2);
            p1 = fmaf(w1.z, xv[c4*4+2], p1); p2 = fmaf(w2.z, xv[c4*4+2], p2);
            p1 = fmaf(w1.w, xv[c4*4+3], p1); p2 = fmaf(w2.w, xv[c4*4+3], p2);
        }
        float nu  = __logf(1.f + __expf(p1));
        float e2  = __expf(2.f * p2);
        float ang = pdt - __fdividef(2.f * pdt, e2 + 1.f);
        float dec = __expf(-nu * dtb);
        float s, co; __sincosf(ang, &s, &co);
        fr = fmaf(dec, co, fr);
        fi = fmaf(dec, s, fi);
    }
    d_G[id] = make_float2((fr - 1.f) * 0.00390625f, fi * 0.00390625f);
}

// ---------------- fused H transform: V = IFFT_256( G .* FFT_256(U) ) ------------
#define PSTR 9
__global__ void __launch_bounds__(128) k_hfft() {
    __shared__ float SAr[256*PSTR], SAi[256*PSTR];
    __shared__ float SBr[256*PSTR], SBi[256*PSTR];
    __shared__ float2 Ws[256];
    const int bc = blockIdx.x >> 1;
    const int half = blockIdx.x & 1;
    const int b = bc >> 6;
    const int t = threadIdx.x;
    const int kk = t & 7, u = t >> 3;

    for (int i = t; i < 256; i += 128) {
        float2 e = d_E[2 * i];
        Ws[i] = make_float2(e.x, -e.y);
    }
    const float2* Ub = (const float2*)d_U + (size_t)bc * 256 * 64;
    float2*       Vb = (float2*)d_V + (size_t)bc * 256 * 64;

    for (int kb = half * 32; kb < half * 32 + 32; kb += 8) {
        __syncthreads();
        for (int i = t; i < 2048; i += 128) {
            int h = i >> 3, k2 = i & 7;
            float2 uv = Ub[h * 64 + kb + k2];
            SAr[h * PSTR + k2] = uv.x; SAi[h * PSTR + k2] = uv.y;
        }
        __syncthreads();
        float2 v[16];
#pragma unroll
        for (int n2 = 0; n2 < 16; n2++) {
            int p = (u + 16 * n2) * PSTR + kk;
            v[n2] = make_float2(SAr[p], SAi[p]);
        }
        fft16<0>(v);
#pragma unroll
        for (int k2 = 1; k2 < 16; k2++) v[k2] = cmul(v[k2], Ws[u * k2]);
#pragma unroll
        for (int k2 = 0; k2 < 16; k2++) {
            int p = (k2 * 16 + u) * PSTR + kk;
            SBr[p] = v[k2].x; SBi[p] = v[k2].y;
        }
        __syncthreads();
#pragma unroll
        for (int n1 = 0; n1 < 16; n1++) {
            int p = (u * 16 + n1) * PSTR + kk;
            v[n1] = make_float2(SBr[p], SBi[p]);
        }
        fft16<0>(v);
#pragma unroll
        for (int r = 0; r < 16; r++) {
            float2 g = d_G[((size_t)b * 256 + u + 16 * r) * 64 + kb + kk];
            v[r] = cmul(v[r], g);
        }
        fft16<1>(v);
#pragma unroll
        for (int n2 = 0; n2 < 16; n2++) {
            float2 wc = Ws[u * n2]; wc.y = -wc.y;
            float2 r = cmul(v[n2], wc);
            int p = (n2 * 16 + u) * PSTR + kk;
            SAr[p] = r.x; SAi[p] = r.y;
        }
        __syncthreads();
#pragma unroll
        for (int m1 = 0; m1 < 16; m1++) {
            int p = (u * 16 + m1) * PSTR + kk;
            v[m1] = make_float2(SAr[p], SAi[p]);
        }
        fft16<1>(v);
#pragma unroll
        for (int n1 = 0; n1 < 16; n1++)
            Vb[(u + 16 * n1) * 64 + kb + kk] = v[n1];
    }
}

// ---------------- K5 inverse: plane-split groups + smem exchange ----------------
// SM layout phase-1: VRe/VIe/VRo/VIo [16][68] then BPe/BPo/BQe/BQo [16][64]
// phase-2 (exchange): 128 threads x stride 70
__global__ void __launch_bounds__(256) k_inv(const float* __restrict__ x,
                                             float* __restrict__ out) {
    __shared__ float SM[8960];
    float* VRe = SM;            float* VIe = SM + 1088;
    float* VRo = SM + 2176;     float* VIo = SM + 3264;
    float* BPe = SM + 4352;     float* BPo = SM + 5376;
    float* BQe = SM + 6400;     float* BQo = SM + 7424;
    const int tid = threadIdx.x;
    const int grp = tid >> 7;           // 0: (Pe,Qe)  1: (Po,Qo)
    const int idx = tid & 127;
    const int rg  = idx >> 4;           // 8 row groups x 8 rows
    const int ng  = idx & 15;           // 16 n groups x 4 n
    const long row0 = (long)blockIdx.x * 64;
    const int n0 = blockIdx.y * 64;

    float P[8][4], Q[8][4];
#pragma unroll
    for (int m = 0; m < 8; m++)
#pragma unroll
        for (int w = 0; w < 4; w++) { P[m][w] = 0.f; Q[m][w] = 0.f; }

    for (int jc = 0; jc < 32; jc += 16) {
        __syncthreads();
#pragma unroll
        for (int i = 0; i < 4; i++) {   // V chunk -> 4 planes
            int f = tid + i * 256;
            int r = f >> 4, jl = f & 15;
            float4 v = *(const float4*)&d_V[(row0 + r) * 128 + (jc + jl) * 4];
            VRe[jl * 68 + r] = v.x; VIe[jl * 68 + r] = v.y;
            VRo[jl * 68 + r] = v.z; VIo[jl * 68 + r] = v.w;
        }
#pragma unroll
        for (int i = 0; i < 4; i++) {   // B tables
            int f = tid + i * 256;
            int which = f >> 8, gg = f & 255;
            int jl = gg >> 4, n4 = (gg & 15) * 4;
            const float* src =
                (which == 0 ? d_Ipe : which == 1 ? d_Ipo : which == 2 ? d_Iqe : d_Iqo)
                + (jc + jl) * 128 + n0 + n4;
            float* dst = (which == 0 ? BPe : which == 1 ? BPo
                        : which == 2 ? BQe : BQo) + jl * 64 + n4;
            *(float4*)dst = *(const float4*)src;
        }
        __syncthreads();
        const float* Vr = grp ? VRo : VRe;
        const float* Vi = grp ? VIo : VIe;
        const float* Bp = grp ? BPo : BPe;
        const float* Bq = grp ? BQo : BQe;
#pragma unroll
        for (int jl = 0; jl < 16; jl++) {
            float4 r0 = *(const float4*)(Vr + jl * 68 + rg * 8);
            float4 r1 = *(const float4*)(Vr + jl * 68 + rg * 8 + 4);
            float4 i0 = *(const float4*)(Vi + jl * 68 + rg * 8);
            float4 i1 = *(const float4*)(Vi + jl * 68 + rg * 8 + 4);
            float4 bp = *(const float4*)(Bp + jl * 64 + ng * 4);
            float4 bq = *(const float4*)(Bq + jl * 64 + ng * 4);
            float vr[8] = {r0.x,r0.y,r0.z,r0.w,r1.x,r1.y,r1.z,r1.w};
            float vi[8] = {i0.x,i0.y,i0.z,i0.w,i1.x,i1.y,i1.z,i1.w};
            float pv[4] = {bp.x,bp.y,bp.z,bp.w};
            float qv[4] = {bq.x,bq.y,bq.z,bq.w};
#pragma unroll
            for (int m = 0; m < 8; m++)
#pragma unroll
                for (int w = 0; w < 4; w++) {
                    P[m][w] = fmaf(vr[m], pv[w], P[m][w]);
                    Q[m][w] = fmaf(vi[m], qv[w], Q[m][w]);
                }
        }
    }
    __syncthreads();
    if (grp) {                          // O group ships P,Q through smem
        float* e = SM + idx * 70;
#pragma unroll
        for (int m = 0; m < 8; m++)
#pragma unroll
            for (int w = 0; w < 4; w++) {
                e[m * 4 + w]      = P[m][w];
                e[32 + m * 4 + w] = Q[m][w];
            }
    }
    __syncthreads();
    if (!grp) {                         // E group combines + stores everything
        const float* e = SM + idx * 70;
        const float s = 1.f / 512.f;
#pragma unroll
        for (int m = 0; m < 8; m++) {
            long row = row0 + rg * 8 + m;
            const float* xr = x + row * W_;
            float* orow = out + row * W_;
            int nn0 = n0 + ng * 4;
            float4 xf = *(const float4*)(xr + nn0);
            float4 xg = *(const float4*)(xr + 256 + nn0);
            float d1[4], d2[4], d3[4], d4[4];
#pragma unroll
            for (int w = 0; w < 4; w++) {
                float Po = e[m * 4 + w], Qo = e[32 + m * 4 + w];
                float pp = P[m][w] + Po, pm = P[m][w] - Po;
                float qp = Q[m][w] + Qo, qm = Q[m][w] - Qo;
                d1[w] = pp - qp;    // y[n]
                d2[w] = pp + qp;    // y[512-n]
                d3[w] = pm + qm;    // y[256-n]
                d4[w] = pm - qm;    // y[256+n]
            }
            float4 o1, o2;
            o1.x = fmaf(d1[0], s, xf.x); o1.y = fmaf(d1[1], s, xf.y);
            o1.z = fmaf(d1[2], s, xf.z); o1.w = fmaf(d1[3], s, xf.w);
            o2.x = fmaf(d4[0], s, xg.x); o2.y = fmaf(d4[1], s, xg.y);
            o2.z = fmaf(d4[2], s, xg.z); o2.w = fmaf(d4[3], s, xg.w);
            *(float4*)(orow + nn0) = o1;
            *(float4*)(orow + 256 + nn0) = o2;
            {   // mirror 256-n  (range [129,256])
                int b0 = 256 - nn0;
                orow[b0] = fmaf(d3[0], s, xr[b0]);
                float2 mm = *(const float2*)(xr + b0 - 2);
                *(float2*)(orow + b0 - 2) =
                    make_float2(fmaf(d3[2], s, mm.x), fmaf(d3[1], s, mm.y));
                orow[b0 - 3] = fmaf(d3[3], s, xr[b0 - 3]);
            }
            {   // mirror (512-n)&511 (wrap at nn0=0,w=0 writes same value as o1.x)
                int b0 = (512 - nn0) & 511;
                orow[b0] = fmaf(d2[0], s, xr[b0]);
                int b2 = 510 - nn0;
                float2 mm = *(const float2*)(xr + b2);
                *(float2*)(orow + b2) =
                    make_float2(fmaf(d2[2], s, mm.x), fmaf(d2[1], s, mm.y));
                orow[b2 - 1] = fmaf(d2[3], s, xr[b2 - 1]);
            }
        }
    }
}

// ---------------- edge columns 128 & 384 ----------------
__global__ void k_edge(const float* __restrict__ x, float* __restrict__ out) {
    int tid = threadIdx.x;
    int lane = tid & 31, wr = tid >> 5;
    long row = (long)blockIdx.x * 8 + wr;
    float4 v = *(const float4*)&d_V[row * 128 + lane * 4];
    float sg = (lane & 1) ? -1.f : 1.f;
    float pe = ((lane == 0) ? 1.f : 2.f) * sg * v.x;
    float qo = 2.f * sg * v.w;
#pragma unroll
    for (int o = 16; o > 0; o >>= 1) {
        pe += __shfl_down_sync(0xffffffffu, pe, o);
        qo += __shfl_down_sync(0xffffffffu, qo, o);
    }
    if (lane == 0) {
        const float s = 1.f / 512.f;
        out[row * W_ + 128] = fmaf(pe - qo, s, x[row * W_ + 128]);
        out[row * W_ + 384] = fmaf(pe + qo, s, x[row * W_ + 384]);
    }
}

// ---------------- launch ----------------
extern "C" void kernel_launch(void* const* d_in, const int* in_sizes, int n_in,
                              void* d_out, int out_size) {
    const float* x    = (const float*)d_in[0];
    const float* dt   = (const float*)d_in[1];
    const float* w    = (const float*)d_in[2];
    const float* bias = (const float*)d_in[3];
    float* out = (float*)d_out;

    k_tables<<<128, 256>>>();
    k_fwd<<<NROW / 128, 256>>>(x);      // also writes d_xp (fused pooling)
    k_filter<<<B_ * H_ * KF / 256, 256>>>(w, bias, dt);
    k_hfft<<<B_ * C_ * 2, 128>>>();
    k_inv<<<dim3(NROW / 64, 2), 256>>>(x, out);
    k_edge<<<NROW / 8, 256>>>(x, out);
}